// round 11
// baseline (speedup 1.0000x reference)
#include <cuda_runtime.h>
#include <cuda_bf16.h>
#include <math.h>
#include <stdint.h>

// Problem shape (fixed by setup_inputs)
#define SDIM 2048
#define RDIM 512
#define CDIM 64
#define NSBLK 16           // SDIM/128 blocks per r in kernel A

// ---------------- device scratch (no allocs allowed) ----------------
static __device__ float g_poolp[RDIM][NSBLK][64];        // per-(r, sblk) pool partials
static __device__ float g_msump[RDIM][NSBLK];            // per-(r, sblk) mask-sum partials
static __device__ float g_kv[(size_t)RDIM * SDIM * 16];  // [r][s][j]; j<8: k, j>=8: v
static __device__ float g_ovec[RDIM * CDIM];             // per r: o[h*8+ch]

__device__ __forceinline__ float sigm(float x) {
    float t = __expf(-x);
    return __fdividef(1.f, 1.f + t);
}
__device__ __forceinline__ void mma_bf16(float d[4],
    uint32_t a0, uint32_t a1, uint32_t a2, uint32_t a3,
    uint32_t b0, uint32_t b1)
{
    asm volatile(
        "mma.sync.aligned.m16n8k16.row.col.f32.bf16.bf16.f32 "
        "{%0,%1,%2,%3}, {%4,%5,%6,%7}, {%8,%9}, {%0,%1,%2,%3};"
        : "+f"(d[0]), "+f"(d[1]), "+f"(d[2]), "+f"(d[3])
        : "r"(a0), "r"(a1), "r"(a2), "r"(a3), "r"(b0), "r"(b1));
}
__device__ __forceinline__ uint32_t ld32s(const __nv_bfloat16* p) {
    return *(const uint32_t*)p;
}
__device__ __forceinline__ uint32_t pack_hi2(float x, float y) {
    __nv_bfloat16 hx = __float2bfloat16(x), hy = __float2bfloat16(y);
    return (uint32_t)__bfloat16_as_ushort(hx) | ((uint32_t)__bfloat16_as_ushort(hy) << 16);
}
__device__ __forceinline__ uint32_t pack_lo2(float x, float y) {
    __nv_bfloat16 hx = __float2bfloat16(x), hy = __float2bfloat16(y);
    __nv_bfloat16 lx = __float2bfloat16(x - __bfloat162float(hx));
    __nv_bfloat16 ly = __float2bfloat16(y - __bfloat162float(hy));
    return (uint32_t)__bfloat16_as_ushort(lx) | ((uint32_t)__bfloat16_as_ushort(ly) << 16);
}

// ========== kernel A: LN + masked pool + K/V via HMMA (unchanged) ==========
#define ASTR 72
__global__ void __launch_bounds__(256) k_pool_kv(
    const float* __restrict__ m, const float* __restrict__ mask,
    const float* __restrict__ ln_w, const float* __restrict__ ln_b,
    const float* __restrict__ wk, const float* __restrict__ wv)
{
    __shared__ __nv_bfloat16 s_ah[128 * ASTR];   // XN hi, row-major [row][c]
    __shared__ __nv_bfloat16 s_al[128 * ASTR];   // XN lo
    __shared__ __nv_bfloat16 s_bh[16 * ASTR];    // wkv^T hi: [j][c]
    __shared__ __nv_bfloat16 s_bl[16 * ASTR];
    __shared__ float s_pool[8][64];
    __shared__ float s_ms[8];

    const int r    = blockIdx.y;
    const int s0   = blockIdx.x * 128;
    const int tid  = threadIdx.x;
    const int lane = tid & 31;
    const int w    = tid >> 5;
    const int g    = lane >> 2;
    const int tig  = lane & 3;

    for (int idx = tid; idx < 1024; idx += 256) {
        int j = idx >> 6, c = idx & 63;
        float v = (j < 8) ? __ldg(&wk[c * 8 + j]) : __ldg(&wv[c * 8 + (j - 8)]);
        __nv_bfloat16 h = __float2bfloat16(v);
        s_bh[j * ASTR + c] = h;
        s_bl[j * ASTR + c] = __float2bfloat16(v - __bfloat162float(h));
    }

    const float lw0 = ln_w[lane], lw1 = ln_w[lane + 32];
    const float lb0 = ln_b[lane], lb1 = ln_b[lane + 32];
    float p0 = 0.f, p1 = 0.f, pm = 0.f;
    #pragma unroll
    for (int i = 0; i < 16; ++i) {
        const int row = w * 16 + i;
        const int s   = s0 + row;
        const float* mp = m + ((size_t)s * RDIM + r) * CDIM;
        float x0 = mp[lane];
        float x1 = mp[lane + 32];
        float mv = __ldg(&mask[s * RDIM + r]);

        float sum = x0 + x1;
        #pragma unroll
        for (int o = 16; o; o >>= 1) sum += __shfl_xor_sync(0xffffffffu, sum, o);
        float mu = sum * (1.f / 64.f);
        float d0 = x0 - mu, d1 = x1 - mu;
        float vv = d0 * d0 + d1 * d1;
        #pragma unroll
        for (int o = 16; o; o >>= 1) vv += __shfl_xor_sync(0xffffffffu, vv, o);
        float rstd = rsqrtf(vv * (1.f / 64.f) + 1e-5f);
        float xn0 = d0 * rstd * lw0 + lb0;
        float xn1 = d1 * rstd * lw1 + lb1;

        __nv_bfloat16 h0 = __float2bfloat16(xn0);
        __nv_bfloat16 h1 = __float2bfloat16(xn1);
        s_ah[row * ASTR + lane]      = h0;
        s_ah[row * ASTR + lane + 32] = h1;
        s_al[row * ASTR + lane]      = __float2bfloat16(xn0 - __bfloat162float(h0));
        s_al[row * ASTR + lane + 32] = __float2bfloat16(xn1 - __bfloat162float(h1));
        p0 += xn0 * mv;
        p1 += xn1 * mv;
        pm += mv;   // identical across lanes
    }
    s_pool[w][lane]      = p0;
    s_pool[w][lane + 32] = p1;
    if (lane == 0) s_ms[w] = pm;
    __syncthreads();

    if (tid < 64) {
        float a = 0.f;
        #pragma unroll
        for (int k = 0; k < 8; ++k) a += s_pool[k][tid];
        g_poolp[r][blockIdx.x][tid] = a;
    }
    if (tid == 0) {
        float a = 0.f;
        #pragma unroll
        for (int k = 0; k < 8; ++k) a += s_ms[k];
        g_msump[r][blockIdx.x] = a;
    }

    const int ar0 = w * 16 + g;
    float acc[2][4];
    #pragma unroll
    for (int nt = 0; nt < 2; ++nt)
        #pragma unroll
        for (int q = 0; q < 4; ++q) acc[nt][q] = 0.f;

    #pragma unroll
    for (int kk = 0; kk < 4; ++kk) {
        const int k0 = kk * 16 + tig * 2;
        uint32_t ah0 = ld32s(&s_ah[ar0 * ASTR + k0]);
        uint32_t ah1 = ld32s(&s_ah[(ar0 + 8) * ASTR + k0]);
        uint32_t ah2 = ld32s(&s_ah[ar0 * ASTR + k0 + 8]);
        uint32_t ah3 = ld32s(&s_ah[(ar0 + 8) * ASTR + k0 + 8]);
        uint32_t al0 = ld32s(&s_al[ar0 * ASTR + k0]);
        uint32_t al1 = ld32s(&s_al[(ar0 + 8) * ASTR + k0]);
        uint32_t al2 = ld32s(&s_al[ar0 * ASTR + k0 + 8]);
        uint32_t al3 = ld32s(&s_al[(ar0 + 8) * ASTR + k0 + 8]);
        #pragma unroll
        for (int nt = 0; nt < 2; ++nt) {
            const int n = nt * 8 + g;
            uint32_t bh0 = ld32s(&s_bh[n * ASTR + k0]);
            uint32_t bh1 = ld32s(&s_bh[n * ASTR + k0 + 8]);
            uint32_t bl0 = ld32s(&s_bl[n * ASTR + k0]);
            uint32_t bl1 = ld32s(&s_bl[n * ASTR + k0 + 8]);
            mma_bf16(acc[nt], ah0, ah1, ah2, ah3, bh0, bh1);
            mma_bf16(acc[nt], ah0, ah1, ah2, ah3, bl0, bl1);
            mma_bf16(acc[nt], al0, al1, al2, al3, bh0, bh1);
        }
    }
    #pragma unroll
    for (int nt = 0; nt < 2; ++nt) {
        const int j0 = nt * 8 + tig * 2;
        const int sr = s0 + ar0;
        float* p0 = g_kv + ((size_t)r * SDIM + sr) * 16 + j0;
        float* p1 = g_kv + ((size_t)r * SDIM + sr + 8) * 16 + j0;
        *(float2*)p0 = make_float2(acc[nt][0], acc[nt][1]);
        *(float2*)p1 = make_float2(acc[nt][2], acc[nt][3]);
    }
}

// ---------------- kernel B: pool reduce, q, softmax over S, o (unchanged) ----
__global__ void __launch_bounds__(256) k_attn(
    const float* __restrict__ mask, const float* __restrict__ wq)
{
    const int r   = blockIdx.x;
    const int tid = threadIdx.x;
    const int lane = tid & 31;
    const int h    = tid >> 5;

    __shared__ float s_p[64];
    __shared__ float s_red[256];
    __shared__ float s_minv;

    if (tid < 32) {
        float mm = (lane < NSBLK) ? g_msump[r][lane] : 0.f;
        #pragma unroll
        for (int o = 16; o; o >>= 1) mm += __shfl_xor_sync(0xffffffffu, mm, o);
        if (lane == 0) s_minv = __fdividef(1.f, mm + 1e-10f);
    }
    {
        int c = tid & 63, gp = tid >> 6;
        float a = 0.f;
        #pragma unroll
        for (int k = 0; k < 4; ++k) a += g_poolp[r][gp * 4 + k][c];
        s_red[tid] = a;
    }
    __syncthreads();
    if (tid < 64)
        s_p[tid] = (s_red[tid] + s_red[tid + 64] + s_red[tid + 128] + s_red[tid + 192]) * s_minv;
    __syncthreads();

    float q[8];
    float pc0 = s_p[lane], pc1 = s_p[lane + 32];
    #pragma unroll
    for (int j = 0; j < 8; ++j)
        q[j] = pc0 * wq[lane * 64 + h * 8 + j] + pc1 * wq[(lane + 32) * 64 + h * 8 + j];
    #pragma unroll
    for (int o = 16; o; o >>= 1) {
        #pragma unroll
        for (int j = 0; j < 8; ++j) q[j] += __shfl_xor_sync(0xffffffffu, q[j], o);
    }
    #pragma unroll
    for (int j = 0; j < 8; ++j) q[j] *= 0.35355339059327373f;

    const float LOG2E = 1.4426950408889634f;
    float M = -1e30f, L = 0.f;
    float acc[8];
    #pragma unroll
    for (int j = 0; j < 8; ++j) acc[j] = 0.f;

    for (int t = 0; t < SDIM / 32; ++t) {
        int s = t * 32 + lane;
        const float4* kv = (const float4*)(g_kv + ((size_t)r * SDIM + s) * 16);
        float4 k0 = kv[0], k1 = kv[1];
        float4 v0 = kv[2], v1 = kv[3];
        float mv = __ldg(&mask[s * RDIM + r]);
        float logit = q[0]*k0.x + q[1]*k0.y + q[2]*k0.z + q[3]*k0.w
                    + q[4]*k1.x + q[5]*k1.y + q[6]*k1.z + q[7]*k1.w
                    + 1e9f * (mv - 1.f);
        float nM = fmaxf(M, logit);
        float sc = exp2f((M - nM) * LOG2E);
        float p  = exp2f((logit - nM) * LOG2E);
        L = L * sc + p;
        acc[0] = acc[0]*sc + p*v0.x; acc[1] = acc[1]*sc + p*v0.y;
        acc[2] = acc[2]*sc + p*v0.z; acc[3] = acc[3]*sc + p*v0.w;
        acc[4] = acc[4]*sc + p*v1.x; acc[5] = acc[5]*sc + p*v1.y;
        acc[6] = acc[6]*sc + p*v1.z; acc[7] = acc[7]*sc + p*v1.w;
        M = nM;
    }
    float Mm = M;
    #pragma unroll
    for (int o = 16; o; o >>= 1) Mm = fmaxf(Mm, __shfl_xor_sync(0xffffffffu, Mm, o));
    float sc = exp2f((M - Mm) * LOG2E);
    L *= sc;
    #pragma unroll
    for (int j = 0; j < 8; ++j) acc[j] *= sc;
    #pragma unroll
    for (int o = 16; o; o >>= 1) {
        L += __shfl_xor_sync(0xffffffffu, L, o);
        #pragma unroll
        for (int j = 0; j < 8; ++j) acc[j] += __shfl_xor_sync(0xffffffffu, acc[j], o);
    }
    if (lane == 0) {
        float inv = 1.f / L;
        #pragma unroll
        for (int j = 0; j < 8; ++j) g_ovec[r * 64 + h * 8 + j] = acc[j] * inv;
    }
}

// ===== kernel C: HMMA 3-pass split, 512 threads, N split across warp pairs =====
#define AS 72
#define BS 72
#define SMC_BYTES (2*128*AS*2 + 2*64*BS*2 + 2*64*4)   // 55808 B

__global__ void __launch_bounds__(512) k_out_mma(
    const float* __restrict__ m,
    const float* __restrict__ ln_w, const float* __restrict__ ln_b,
    const float* __restrict__ wg, const float* __restrict__ bg,
    const float* __restrict__ wo, const float* __restrict__ bo,
    float* __restrict__ out)
{
    extern __shared__ __align__(16) uint8_t smraw[];
    __nv_bfloat16* s_ah = (__nv_bfloat16*)smraw;       // [128][AS] X hi / later G hi
    __nv_bfloat16* s_al = s_ah + 128 * AS;             // [128][AS] X lo / later G lo
    __nv_bfloat16* s_bh = s_al + 128 * AS;             // [64][BS]  B hi (wg^T, then (ov.*wo)^T)
    __nv_bfloat16* s_bl = s_bh + 64 * BS;
    float*         s_bg = (float*)(s_bl + 64 * BS);
    float*         s_bo = s_bg + 64;

    const int r     = blockIdx.y;
    const int s0    = blockIdx.x * 128;
    const int tid   = threadIdx.x;
    const int lane  = tid & 31;
    const int w     = tid >> 5;      // 0..15
    const int rt    = w >> 1;        // row tile 0..7 (rows rt*16..+15)
    const int nhalf = w & 1;         // n-tile half: nt = nhalf*4 + 0..3
    const int g     = lane >> 2;
    const int tig   = lane & 3;

    // stage B1 = wg^T (hi/lo)
    for (int idx = tid; idx < 4096; idx += 512) {
        int c = idx >> 6, j = idx & 63;
        float x = __ldg(&wg[idx]);
        __nv_bfloat16 h1 = __float2bfloat16(x);
        s_bh[j * BS + c] = h1;
        s_bl[j * BS + c] = __float2bfloat16(x - __bfloat162float(h1));
    }
    if (tid < 64) { s_bg[tid] = bg[tid]; s_bo[tid] = bo[tid]; }

    // LayerNorm: warp per row, 8 rows per warp
    const float lw0 = ln_w[lane], lw1 = ln_w[lane + 32];
    const float lb0 = ln_b[lane], lb1 = ln_b[lane + 32];
    #pragma unroll
    for (int i = 0; i < 8; ++i) {
        const int row = w * 8 + i;
        const int s   = s0 + row;
        const float* mp = m + ((size_t)s * RDIM + r) * CDIM;
        float x0 = mp[lane];
        float x1 = mp[lane + 32];
        float sum = x0 + x1;
        #pragma unroll
        for (int o = 16; o; o >>= 1) sum += __shfl_xor_sync(0xffffffffu, sum, o);
        float mu = sum * (1.f / 64.f);
        float d0 = x0 - mu, d1 = x1 - mu;
        float vv = d0 * d0 + d1 * d1;
        #pragma unroll
        for (int o = 16; o; o >>= 1) vv += __shfl_xor_sync(0xffffffffu, vv, o);
        float rstd = rsqrtf(vv * (1.f / 64.f) + 1e-5f);
        float xn0 = d0 * rstd * lw0 + lb0;
        float xn1 = d1 * rstd * lw1 + lb1;
        __nv_bfloat16 h0 = __float2bfloat16(xn0);
        __nv_bfloat16 h1 = __float2bfloat16(xn1);
        s_ah[row * AS + lane]      = h0;
        s_ah[row * AS + lane + 32] = h1;
        s_al[row * AS + lane]      = __float2bfloat16(xn0 - __bfloat162float(h0));
        s_al[row * AS + lane + 32] = __float2bfloat16(xn1 - __bfloat162float(h1));
    }
    __syncthreads();

    const int ar0 = rt * 16 + g;

    // GEMM1: pre = XN @ wg   (this warp: 4 n-tiles)
    float acc[4][4];
    #pragma unroll
    for (int nt = 0; nt < 4; ++nt)
        #pragma unroll
        for (int q = 0; q < 4; ++q) acc[nt][q] = 0.f;

    #pragma unroll
    for (int kk = 0; kk < 4; ++kk) {
        const int k0 = kk * 16 + tig * 2;
        uint32_t ah0 = ld32s(&s_ah[ar0 * AS + k0]);
        uint32_t ah1 = ld32s(&s_ah[(ar0 + 8) * AS + k0]);
        uint32_t ah2 = ld32s(&s_ah[ar0 * AS + k0 + 8]);
        uint32_t ah3 = ld32s(&s_ah[(ar0 + 8) * AS + k0 + 8]);
        uint32_t al0 = ld32s(&s_al[ar0 * AS + k0]);
        uint32_t al1 = ld32s(&s_al[(ar0 + 8) * AS + k0]);
        uint32_t al2 = ld32s(&s_al[ar0 * AS + k0 + 8]);
        uint32_t al3 = ld32s(&s_al[(ar0 + 8) * AS + k0 + 8]);
        #pragma unroll
        for (int nt = 0; nt < 4; ++nt) {
            const int n = (nhalf * 4 + nt) * 8 + g;
            uint32_t bh0 = ld32s(&s_bh[n * BS + k0]);
            uint32_t bh1 = ld32s(&s_bh[n * BS + k0 + 8]);
            uint32_t bl0 = ld32s(&s_bl[n * BS + k0]);
            uint32_t bl1 = ld32s(&s_bl[n * BS + k0 + 8]);
            mma_bf16(acc[nt], ah0, ah1, ah2, ah3, bh0, bh1);
            mma_bf16(acc[nt], ah0, ah1, ah2, ah3, bl0, bl1);
            mma_bf16(acc[nt], al0, al1, al2, al3, bh0, bh1);
        }
    }
    __syncthreads();   // all GEMM1 reads (A and B tiles) complete

    // epilogue 1: G = sigmoid(pre + bg) -> overwrite A tiles (disjoint cols per warp)
    #pragma unroll
    for (int nt = 0; nt < 4; ++nt) {
        const int col = (nhalf * 4 + nt) * 8 + tig * 2;
        float v0 = sigm(acc[nt][0] + s_bg[col]);
        float v1 = sigm(acc[nt][1] + s_bg[col + 1]);
        float v2 = sigm(acc[nt][2] + s_bg[col]);
        float v3 = sigm(acc[nt][3] + s_bg[col + 1]);
        *(uint32_t*)&s_ah[ar0 * AS + col]       = pack_hi2(v0, v1);
        *(uint32_t*)&s_al[ar0 * AS + col]       = pack_lo2(v0, v1);
        *(uint32_t*)&s_ah[(ar0 + 8) * AS + col] = pack_hi2(v2, v3);
        *(uint32_t*)&s_al[(ar0 + 8) * AS + col] = pack_lo2(v2, v3);
    }
    // restage B2 = (ov .* wo)^T into the same B buffers
    {
        const float* ov = g_ovec + r * 64;
        for (int idx = tid; idx < 4096; idx += 512) {
            int jj = idx >> 6, cc = idx & 63;
            float y = __ldg(&ov[jj]) * __ldg(&wo[idx]);
            __nv_bfloat16 h2 = __float2bfloat16(y);
            s_bh[cc * BS + jj] = h2;
            s_bl[cc * BS + jj] = __float2bfloat16(y - __bfloat162float(h2));
        }
    }
    __syncthreads();

    // GEMM2: out = G @ (ov.*wo) + bo
    float acc2[4][4];
    #pragma unroll
    for (int nt = 0; nt < 4; ++nt)
        #pragma unroll
        for (int q = 0; q < 4; ++q) acc2[nt][q] = 0.f;

    #pragma unroll
    for (int kk = 0; kk < 4; ++kk) {
        const int k0 = kk * 16 + tig * 2;
        uint32_t ah0 = ld32s(&s_ah[ar0 * AS + k0]);
        uint32_t ah1 = ld32s(&s_ah[(ar0 + 8) * AS + k0]);
        uint32_t ah2 = ld32s(&s_ah[ar0 * AS + k0 + 8]);
        uint32_t ah3 = ld32s(&s_ah[(ar0 + 8) * AS + k0 + 8]);
        uint32_t al0 = ld32s(&s_al[ar0 * AS + k0]);
        uint32_t al1 = ld32s(&s_al[(ar0 + 8) * AS + k0]);
        uint32_t al2 = ld32s(&s_al[ar0 * AS + k0 + 8]);
        uint32_t al3 = ld32s(&s_al[(ar0 + 8) * AS + k0 + 8]);
        #pragma unroll
        for (int nt = 0; nt < 4; ++nt) {
            const int n = (nhalf * 4 + nt) * 8 + g;
            uint32_t bh0 = ld32s(&s_bh[n * BS + k0]);
            uint32_t bh1 = ld32s(&s_bh[n * BS + k0 + 8]);
            uint32_t bl0 = ld32s(&s_bl[n * BS + k0]);
            uint32_t bl1 = ld32s(&s_bl[n * BS + k0 + 8]);
            mma_bf16(acc2[nt], ah0, ah1, ah2, ah3, bh0, bh1);
            mma_bf16(acc2[nt], ah0, ah1, ah2, ah3, bl0, bl1);
            mma_bf16(acc2[nt], al0, al1, al2, al3, bh0, bh1);
        }
    }

    // final store: + bo
    {
        const int row0 = s0 + ar0;
        float* op0 = out + ((size_t)row0 * RDIM + r) * CDIM;
        float* op1 = out + ((size_t)(row0 + 8) * RDIM + r) * CDIM;
        #pragma unroll
        for (int nt = 0; nt < 4; ++nt) {
            const int col = (nhalf * 4 + nt) * 8 + tig * 2;
            float b0 = s_bo[col], b1 = s_bo[col + 1];
            *(float2*)(op0 + col) = make_float2(acc2[nt][0] + b0, acc2[nt][1] + b1);
            *(float2*)(op1 + col) = make_float2(acc2[nt][2] + b0, acc2[nt][3] + b1);
        }
    }
}

// ---------------------------------------------------------------------
extern "C" void kernel_launch(void* const* d_in, const int* in_sizes, int n_in,
                              void* d_out, int out_size) {
    const float* m    = (const float*)d_in[0];
    const float* mask = (const float*)d_in[1];
    const float* ln_w = (const float*)d_in[2];
    const float* ln_b = (const float*)d_in[3];
    const float* wq   = (const float*)d_in[4];
    const float* wk   = (const float*)d_in[5];
    const float* wv   = (const float*)d_in[6];
    const float* wg   = (const float*)d_in[7];
    const float* bg   = (const float*)d_in[8];
    const float* wo   = (const float*)d_in[9];
    const float* bo   = (const float*)d_in[10];
    float* out = (float*)d_out;

    cudaFuncSetAttribute(k_out_mma, cudaFuncAttributeMaxDynamicSharedMemorySize, SMC_BYTES);

    dim3 gA(NSBLK, RDIM);
    k_pool_kv<<<gA, 256>>>(m, mask, ln_w, ln_b, wk, wv);
    k_attn<<<RDIM, 256>>>(mask, wq);
    dim3 gC(SDIM / 128, RDIM);
    k_out_mma<<<gC, 512, SMC_BYTES>>>(m, ln_w, ln_b, wg, bg, wo, bo, out);
}

// round 12
// speedup vs baseline: 1.1426x; 1.1426x over previous
#include <cuda_runtime.h>
#include <cuda_bf16.h>
#include <math.h>
#include <stdint.h>

// Problem shape (fixed by setup_inputs)
#define SDIM 2048
#define RDIM 512
#define CDIM 64
#define NSBLK 16           // SDIM/128 blocks per r in kernel A

// ---------------- device scratch (no allocs allowed) ----------------
static __device__ float g_poolp[RDIM][NSBLK][64];        // per-(r, sblk) pool partials
static __device__ float g_msump[RDIM][NSBLK];            // per-(r, sblk) mask-sum partials
static __device__ float g_kv[(size_t)RDIM * SDIM * 16];  // [r][s][j]; j<8: k, j>=8: v
static __device__ float g_ovec[RDIM * CDIM];             // per r: o[h*8+ch]

__device__ __forceinline__ float sigm(float x) {
    float t = __expf(-x);
    return __fdividef(1.f, 1.f + t);
}
__device__ __forceinline__ void mma_bf16(float d[4],
    uint32_t a0, uint32_t a1, uint32_t a2, uint32_t a3,
    uint32_t b0, uint32_t b1)
{
    asm volatile(
        "mma.sync.aligned.m16n8k16.row.col.f32.bf16.bf16.f32 "
        "{%0,%1,%2,%3}, {%4,%5,%6,%7}, {%8,%9}, {%0,%1,%2,%3};"
        : "+f"(d[0]), "+f"(d[1]), "+f"(d[2]), "+f"(d[3])
        : "r"(a0), "r"(a1), "r"(a2), "r"(a3), "r"(b0), "r"(b1));
}
__device__ __forceinline__ uint32_t ld32s(const __nv_bfloat16* p) {
    return *(const uint32_t*)p;
}
__device__ __forceinline__ uint32_t pack_hi2(float x, float y) {
    __nv_bfloat16 hx = __float2bfloat16(x), hy = __float2bfloat16(y);
    return (uint32_t)__bfloat16_as_ushort(hx) | ((uint32_t)__bfloat16_as_ushort(hy) << 16);
}
__device__ __forceinline__ uint32_t pack_lo2(float x, float y) {
    __nv_bfloat16 hx = __float2bfloat16(x), hy = __float2bfloat16(y);
    __nv_bfloat16 lx = __float2bfloat16(x - __bfloat162float(hx));
    __nv_bfloat16 ly = __float2bfloat16(y - __bfloat162float(hy));
    return (uint32_t)__bfloat16_as_ushort(lx) | ((uint32_t)__bfloat16_as_ushort(ly) << 16);
}

// ========== kernel A: LN + masked pool + K/V via HMMA (unchanged) ==========
#define ASTR 72
__global__ void __launch_bounds__(256) k_pool_kv(
    const float* __restrict__ m, const float* __restrict__ mask,
    const float* __restrict__ ln_w, const float* __restrict__ ln_b,
    const float* __restrict__ wk, const float* __restrict__ wv)
{
    __shared__ __nv_bfloat16 s_ah[128 * ASTR];   // XN hi, row-major [row][c]
    __shared__ __nv_bfloat16 s_al[128 * ASTR];   // XN lo
    __shared__ __nv_bfloat16 s_bh[16 * ASTR];    // wkv^T hi: [j][c]
    __shared__ __nv_bfloat16 s_bl[16 * ASTR];
    __shared__ float s_pool[8][64];
    __shared__ float s_ms[8];

    const int r    = blockIdx.y;
    const int s0   = blockIdx.x * 128;
    const int tid  = threadIdx.x;
    const int lane = tid & 31;
    const int w    = tid >> 5;
    const int g    = lane >> 2;
    const int tig  = lane & 3;

    for (int idx = tid; idx < 1024; idx += 256) {
        int j = idx >> 6, c = idx & 63;
        float v = (j < 8) ? __ldg(&wk[c * 8 + j]) : __ldg(&wv[c * 8 + (j - 8)]);
        __nv_bfloat16 h = __float2bfloat16(v);
        s_bh[j * ASTR + c] = h;
        s_bl[j * ASTR + c] = __float2bfloat16(v - __bfloat162float(h));
    }

    const float lw0 = ln_w[lane], lw1 = ln_w[lane + 32];
    const float lb0 = ln_b[lane], lb1 = ln_b[lane + 32];
    float p0 = 0.f, p1 = 0.f, pm = 0.f;
    #pragma unroll
    for (int i = 0; i < 16; ++i) {
        const int row = w * 16 + i;
        const int s   = s0 + row;
        const float* mp = m + ((size_t)s * RDIM + r) * CDIM;
        float x0 = mp[lane];
        float x1 = mp[lane + 32];
        float mv = __ldg(&mask[s * RDIM + r]);

        float sum = x0 + x1;
        #pragma unroll
        for (int o = 16; o; o >>= 1) sum += __shfl_xor_sync(0xffffffffu, sum, o);
        float mu = sum * (1.f / 64.f);
        float d0 = x0 - mu, d1 = x1 - mu;
        float vv = d0 * d0 + d1 * d1;
        #pragma unroll
        for (int o = 16; o; o >>= 1) vv += __shfl_xor_sync(0xffffffffu, vv, o);
        float rstd = rsqrtf(vv * (1.f / 64.f) + 1e-5f);
        float xn0 = d0 * rstd * lw0 + lb0;
        float xn1 = d1 * rstd * lw1 + lb1;

        __nv_bfloat16 h0 = __float2bfloat16(xn0);
        __nv_bfloat16 h1 = __float2bfloat16(xn1);
        s_ah[row * ASTR + lane]      = h0;
        s_ah[row * ASTR + lane + 32] = h1;
        s_al[row * ASTR + lane]      = __float2bfloat16(xn0 - __bfloat162float(h0));
        s_al[row * ASTR + lane + 32] = __float2bfloat16(xn1 - __bfloat162float(h1));
        p0 += xn0 * mv;
        p1 += xn1 * mv;
        pm += mv;   // identical across lanes
    }
    s_pool[w][lane]      = p0;
    s_pool[w][lane + 32] = p1;
    if (lane == 0) s_ms[w] = pm;
    __syncthreads();

    if (tid < 64) {
        float a = 0.f;
        #pragma unroll
        for (int k = 0; k < 8; ++k) a += s_pool[k][tid];
        g_poolp[r][blockIdx.x][tid] = a;
    }
    if (tid == 0) {
        float a = 0.f;
        #pragma unroll
        for (int k = 0; k < 8; ++k) a += s_ms[k];
        g_msump[r][blockIdx.x] = a;
    }

    const int ar0 = w * 16 + g;
    float acc[2][4];
    #pragma unroll
    for (int nt = 0; nt < 2; ++nt)
        #pragma unroll
        for (int q = 0; q < 4; ++q) acc[nt][q] = 0.f;

    #pragma unroll
    for (int kk = 0; kk < 4; ++kk) {
        const int k0 = kk * 16 + tig * 2;
        uint32_t ah0 = ld32s(&s_ah[ar0 * ASTR + k0]);
        uint32_t ah1 = ld32s(&s_ah[(ar0 + 8) * ASTR + k0]);
        uint32_t ah2 = ld32s(&s_ah[ar0 * ASTR + k0 + 8]);
        uint32_t ah3 = ld32s(&s_ah[(ar0 + 8) * ASTR + k0 + 8]);
        uint32_t al0 = ld32s(&s_al[ar0 * ASTR + k0]);
        uint32_t al1 = ld32s(&s_al[(ar0 + 8) * ASTR + k0]);
        uint32_t al2 = ld32s(&s_al[ar0 * ASTR + k0 + 8]);
        uint32_t al3 = ld32s(&s_al[(ar0 + 8) * ASTR + k0 + 8]);
        #pragma unroll
        for (int nt = 0; nt < 2; ++nt) {
            const int n = nt * 8 + g;
            uint32_t bh0 = ld32s(&s_bh[n * ASTR + k0]);
            uint32_t bh1 = ld32s(&s_bh[n * ASTR + k0 + 8]);
            uint32_t bl0 = ld32s(&s_bl[n * ASTR + k0]);
            uint32_t bl1 = ld32s(&s_bl[n * ASTR + k0 + 8]);
            mma_bf16(acc[nt], ah0, ah1, ah2, ah3, bh0, bh1);
            mma_bf16(acc[nt], ah0, ah1, ah2, ah3, bl0, bl1);
            mma_bf16(acc[nt], al0, al1, al2, al3, bh0, bh1);
        }
    }
    #pragma unroll
    for (int nt = 0; nt < 2; ++nt) {
        const int j0 = nt * 8 + tig * 2;
        const int sr = s0 + ar0;
        float* p0 = g_kv + ((size_t)r * SDIM + sr) * 16 + j0;
        float* p1 = g_kv + ((size_t)r * SDIM + sr + 8) * 16 + j0;
        *(float2*)p0 = make_float2(acc[nt][0], acc[nt][1]);
        *(float2*)p1 = make_float2(acc[nt][2], acc[nt][3]);
    }
}

// ---------------- kernel B: pool reduce, q, softmax over S, o (unchanged) ----
__global__ void __launch_bounds__(256) k_attn(
    const float* __restrict__ mask, const float* __restrict__ wq)
{
    const int r   = blockIdx.x;
    const int tid = threadIdx.x;
    const int lane = tid & 31;
    const int h    = tid >> 5;

    __shared__ float s_p[64];
    __shared__ float s_red[256];
    __shared__ float s_minv;

    if (tid < 32) {
        float mm = (lane < NSBLK) ? g_msump[r][lane] : 0.f;
        #pragma unroll
        for (int o = 16; o; o >>= 1) mm += __shfl_xor_sync(0xffffffffu, mm, o);
        if (lane == 0) s_minv = __fdividef(1.f, mm + 1e-10f);
    }
    {
        int c = tid & 63, gp = tid >> 6;
        float a = 0.f;
        #pragma unroll
        for (int k = 0; k < 4; ++k) a += g_poolp[r][gp * 4 + k][c];
        s_red[tid] = a;
    }
    __syncthreads();
    if (tid < 64)
        s_p[tid] = (s_red[tid] + s_red[tid + 64] + s_red[tid + 128] + s_red[tid + 192]) * s_minv;
    __syncthreads();

    float q[8];
    float pc0 = s_p[lane], pc1 = s_p[lane + 32];
    #pragma unroll
    for (int j = 0; j < 8; ++j)
        q[j] = pc0 * wq[lane * 64 + h * 8 + j] + pc1 * wq[(lane + 32) * 64 + h * 8 + j];
    #pragma unroll
    for (int o = 16; o; o >>= 1) {
        #pragma unroll
        for (int j = 0; j < 8; ++j) q[j] += __shfl_xor_sync(0xffffffffu, q[j], o);
    }
    #pragma unroll
    for (int j = 0; j < 8; ++j) q[j] *= 0.35355339059327373f;

    const float LOG2E = 1.4426950408889634f;
    float M = -1e30f, L = 0.f;
    float acc[8];
    #pragma unroll
    for (int j = 0; j < 8; ++j) acc[j] = 0.f;

    for (int t = 0; t < SDIM / 32; ++t) {
        int s = t * 32 + lane;
        const float4* kv = (const float4*)(g_kv + ((size_t)r * SDIM + s) * 16);
        float4 k0 = kv[0], k1 = kv[1];
        float4 v0 = kv[2], v1 = kv[3];
        float mv = __ldg(&mask[s * RDIM + r]);
        float logit = q[0]*k0.x + q[1]*k0.y + q[2]*k0.z + q[3]*k0.w
                    + q[4]*k1.x + q[5]*k1.y + q[6]*k1.z + q[7]*k1.w
                    + 1e9f * (mv - 1.f);
        float nM = fmaxf(M, logit);
        float sc = exp2f((M - nM) * LOG2E);
        float p  = exp2f((logit - nM) * LOG2E);
        L = L * sc + p;
        acc[0] = acc[0]*sc + p*v0.x; acc[1] = acc[1]*sc + p*v0.y;
        acc[2] = acc[2]*sc + p*v0.z; acc[3] = acc[3]*sc + p*v0.w;
        acc[4] = acc[4]*sc + p*v1.x; acc[5] = acc[5]*sc + p*v1.y;
        acc[6] = acc[6]*sc + p*v1.z; acc[7] = acc[7]*sc + p*v1.w;
        M = nM;
    }
    float Mm = M;
    #pragma unroll
    for (int o = 16; o; o >>= 1) Mm = fmaxf(Mm, __shfl_xor_sync(0xffffffffu, Mm, o));
    float sc = exp2f((M - Mm) * LOG2E);
    L *= sc;
    #pragma unroll
    for (int j = 0; j < 8; ++j) acc[j] *= sc;
    #pragma unroll
    for (int o = 16; o; o >>= 1) {
        L += __shfl_xor_sync(0xffffffffu, L, o);
        #pragma unroll
        for (int j = 0; j < 8; ++j) acc[j] += __shfl_xor_sync(0xffffffffu, acc[j], o);
    }
    if (lane == 0) {
        float inv = 1.f / L;
        #pragma unroll
        for (int j = 0; j < 8; ++j) g_ovec[r * 64 + h * 8 + j] = acc[j] * inv;
    }
}

// ===== kernel C: HMMA 3-pass split; 4 chunks per block, B1+B2 staged once =====
#define AS 72
#define BS 72
#define SMC_BYTES (2*128*AS*2 + 4*64*BS*2 + 2*64*4)   // 74240 B

__global__ void __launch_bounds__(256) k_out_mma(
    const float* __restrict__ m,
    const float* __restrict__ ln_w, const float* __restrict__ ln_b,
    const float* __restrict__ wg, const float* __restrict__ bg,
    const float* __restrict__ wo, const float* __restrict__ bo,
    float* __restrict__ out)
{
    extern __shared__ __align__(16) uint8_t smraw[];
    __nv_bfloat16* s_ah  = (__nv_bfloat16*)smraw;       // [128][AS] X hi / G hi
    __nv_bfloat16* s_al  = s_ah  + 128 * AS;            // [128][AS] X lo / G lo
    __nv_bfloat16* s_b1h = s_al  + 128 * AS;            // [64][BS]  wg^T hi
    __nv_bfloat16* s_b1l = s_b1h + 64 * BS;
    __nv_bfloat16* s_b2h = s_b1l + 64 * BS;             // [64][BS]  (ov.*wo)^T hi
    __nv_bfloat16* s_b2l = s_b2h + 64 * BS;
    float*         s_bg  = (float*)(s_b2l + 64 * BS);
    float*         s_bo  = s_bg + 64;

    const int r     = blockIdx.y;
    const int sbase = blockIdx.x * 512;    // quarter of S
    const int tid   = threadIdx.x;
    const int lane  = tid & 31;
    const int w     = tid >> 5;
    const int g     = lane >> 2;
    const int tig   = lane & 3;

    // ---- stage B1 = wg^T and B2 = (ov.*wo)^T once ----
    const float* ov = g_ovec + r * 64;
    for (int idx = tid; idx < 4096; idx += 256) {
        int c = idx >> 6, j = idx & 63;            // wg[c][j]
        float x = __ldg(&wg[idx]);
        __nv_bfloat16 h1 = __float2bfloat16(x);
        s_b1h[j * BS + c] = h1;
        s_b1l[j * BS + c] = __float2bfloat16(x - __bfloat162float(h1));

        int jj = c, cc = j;                        // wo[jj][cc]
        float y = __ldg(&ov[jj]) * __ldg(&wo[idx]);
        __nv_bfloat16 h2 = __float2bfloat16(y);
        s_b2h[cc * BS + jj] = h2;
        s_b2l[cc * BS + jj] = __float2bfloat16(y - __bfloat162float(h2));
    }
    if (tid < 64) { s_bg[tid] = bg[tid]; s_bo[tid] = bo[tid]; }
    __syncthreads();

    const float lw0 = ln_w[lane], lw1 = ln_w[lane + 32];
    const float lb0 = ln_b[lane], lb1 = ln_b[lane + 32];
    const int ar0 = w * 16 + g;

    for (int chunk = 0; chunk < 4; ++chunk) {
        const int s0 = sbase + chunk * 128;

        // LayerNorm: warp per row (16 rows/warp)
        #pragma unroll
        for (int i = 0; i < 16; ++i) {
            const int row = w * 16 + i;
            const int s   = s0 + row;
            const float* mp = m + ((size_t)s * RDIM + r) * CDIM;
            float x0 = mp[lane];
            float x1 = mp[lane + 32];
            float sum = x0 + x1;
            #pragma unroll
            for (int o = 16; o; o >>= 1) sum += __shfl_xor_sync(0xffffffffu, sum, o);
            float mu = sum * (1.f / 64.f);
            float d0 = x0 - mu, d1 = x1 - mu;
            float vv = d0 * d0 + d1 * d1;
            #pragma unroll
            for (int o = 16; o; o >>= 1) vv += __shfl_xor_sync(0xffffffffu, vv, o);
            float rstd = rsqrtf(vv * (1.f / 64.f) + 1e-5f);
            float xn0 = d0 * rstd * lw0 + lb0;
            float xn1 = d1 * rstd * lw1 + lb1;
            __nv_bfloat16 h0 = __float2bfloat16(xn0);
            __nv_bfloat16 h1 = __float2bfloat16(xn1);
            s_ah[row * AS + lane]      = h0;
            s_ah[row * AS + lane + 32] = h1;
            s_al[row * AS + lane]      = __float2bfloat16(xn0 - __bfloat162float(h0));
            s_al[row * AS + lane + 32] = __float2bfloat16(xn1 - __bfloat162float(h1));
        }
        __syncthreads();

        // GEMM1: pre = XN @ wg
        float acc[8][4];
        #pragma unroll
        for (int nt = 0; nt < 8; ++nt)
            #pragma unroll
            for (int q = 0; q < 4; ++q) acc[nt][q] = 0.f;

        #pragma unroll
        for (int kk = 0; kk < 4; ++kk) {
            const int k0 = kk * 16 + tig * 2;
            uint32_t ah0 = ld32s(&s_ah[ar0 * AS + k0]);
            uint32_t ah1 = ld32s(&s_ah[(ar0 + 8) * AS + k0]);
            uint32_t ah2 = ld32s(&s_ah[ar0 * AS + k0 + 8]);
            uint32_t ah3 = ld32s(&s_ah[(ar0 + 8) * AS + k0 + 8]);
            uint32_t al0 = ld32s(&s_al[ar0 * AS + k0]);
            uint32_t al1 = ld32s(&s_al[(ar0 + 8) * AS + k0]);
            uint32_t al2 = ld32s(&s_al[ar0 * AS + k0 + 8]);
            uint32_t al3 = ld32s(&s_al[(ar0 + 8) * AS + k0 + 8]);
            #pragma unroll
            for (int nt = 0; nt < 8; ++nt) {
                const int n = nt * 8 + g;
                uint32_t bh0 = ld32s(&s_b1h[n * BS + k0]);
                uint32_t bh1 = ld32s(&s_b1h[n * BS + k0 + 8]);
                uint32_t bl0 = ld32s(&s_b1l[n * BS + k0]);
                uint32_t bl1 = ld32s(&s_b1l[n * BS + k0 + 8]);
                mma_bf16(acc[nt], ah0, ah1, ah2, ah3, bh0, bh1);
                mma_bf16(acc[nt], ah0, ah1, ah2, ah3, bl0, bl1);
                mma_bf16(acc[nt], al0, al1, al2, al3, bh0, bh1);
            }
        }
        __syncthreads();   // GEMM1 reads of A tiles complete

        // epilogue 1: G = sigmoid(pre + bg) -> overwrite A tiles
        #pragma unroll
        for (int nt = 0; nt < 8; ++nt) {
            const int col = nt * 8 + tig * 2;
            float v0 = sigm(acc[nt][0] + s_bg[col]);
            float v1 = sigm(acc[nt][1] + s_bg[col + 1]);
            float v2 = sigm(acc[nt][2] + s_bg[col]);
            float v3 = sigm(acc[nt][3] + s_bg[col + 1]);
            *(uint32_t*)&s_ah[ar0 * AS + col]       = pack_hi2(v0, v1);
            *(uint32_t*)&s_al[ar0 * AS + col]       = pack_lo2(v0, v1);
            *(uint32_t*)&s_ah[(ar0 + 8) * AS + col] = pack_hi2(v2, v3);
            *(uint32_t*)&s_al[(ar0 + 8) * AS + col] = pack_lo2(v2, v3);
        }
        __syncthreads();

        // GEMM2: out = G @ (ov.*wo) + bo
        float acc2[8][4];
        #pragma unroll
        for (int nt = 0; nt < 8; ++nt)
            #pragma unroll
            for (int q = 0; q < 4; ++q) acc2[nt][q] = 0.f;

        #pragma unroll
        for (int kk = 0; kk < 4; ++kk) {
            const int k0 = kk * 16 + tig * 2;
            uint32_t ah0 = ld32s(&s_ah[ar0 * AS + k0]);
            uint32_t ah1 = ld32s(&s_ah[(ar0 + 8) * AS + k0]);
            uint32_t ah2 = ld32s(&s_ah[ar0 * AS + k0 + 8]);
            uint32_t ah3 = ld32s(&s_ah[(ar0 + 8) * AS + k0 + 8]);
            uint32_t al0 = ld32s(&s_al[ar0 * AS + k0]);
            uint32_t al1 = ld32s(&s_al[(ar0 + 8) * AS + k0]);
            uint32_t al2 = ld32s(&s_al[ar0 * AS + k0 + 8]);
            uint32_t al3 = ld32s(&s_al[(ar0 + 8) * AS + k0 + 8]);
            #pragma unroll
            for (int nt = 0; nt < 8; ++nt) {
                const int n = nt * 8 + g;
                uint32_t bh0 = ld32s(&s_b2h[n * BS + k0]);
                uint32_t bh1 = ld32s(&s_b2h[n * BS + k0 + 8]);
                uint32_t bl0 = ld32s(&s_b2l[n * BS + k0]);
                uint32_t bl1 = ld32s(&s_b2l[n * BS + k0 + 8]);
                mma_bf16(acc2[nt], ah0, ah1, ah2, ah3, bh0, bh1);
                mma_bf16(acc2[nt], ah0, ah1, ah2, ah3, bl0, bl1);
                mma_bf16(acc2[nt], al0, al1, al2, al3, bh0, bh1);
            }
        }

        // final store: + bo
        {
            const int row0 = s0 + ar0;
            float* op0 = out + ((size_t)row0 * RDIM + r) * CDIM;
            float* op1 = out + ((size_t)(row0 + 8) * RDIM + r) * CDIM;
            #pragma unroll
            for (int nt = 0; nt < 8; ++nt) {
                const int col = nt * 8 + tig * 2;
                float b0 = s_bo[col], b1 = s_bo[col + 1];
                *(float2*)(op0 + col) = make_float2(acc2[nt][0] + b0, acc2[nt][1] + b1);
                *(float2*)(op1 + col) = make_float2(acc2[nt][2] + b0, acc2[nt][3] + b1);
            }
        }
        __syncthreads();   // GEMM2 reads of A(G) tiles complete before next LN overwrites
    }
}

// ---------------------------------------------------------------------
extern "C" void kernel_launch(void* const* d_in, const int* in_sizes, int n_in,
                              void* d_out, int out_size) {
    const float* m    = (const float*)d_in[0];
    const float* mask = (const float*)d_in[1];
    const float* ln_w = (const float*)d_in[2];
    const float* ln_b = (const float*)d_in[3];
    const float* wq   = (const float*)d_in[4];
    const float* wk   = (const float*)d_in[5];
    const float* wv   = (const float*)d_in[6];
    const float* wg   = (const float*)d_in[7];
    const float* bg   = (const float*)d_in[8];
    const float* wo   = (const float*)d_in[9];
    const float* bo   = (const float*)d_in[10];
    float* out = (float*)d_out;

    cudaFuncSetAttribute(k_out_mma, cudaFuncAttributeMaxDynamicSharedMemorySize, SMC_BYTES);

    dim3 gA(NSBLK, RDIM);
    k_pool_kv<<<gA, 256>>>(m, mask, ln_w, ln_b, wk, wv);
    k_attn<<<RDIM, 256>>>(mask, wq);
    dim3 gC(4, RDIM);
    k_out_mma<<<gC, 256, SMC_BYTES>>>(m, ln_w, ln_b, wg, bg, wo, bo, out);
}

// round 13
// speedup vs baseline: 1.1775x; 1.0305x over previous
#include <cuda_runtime.h>
#include <cuda_bf16.h>
#include <math.h>
#include <stdint.h>

// Problem shape (fixed by setup_inputs)
#define SDIM 2048
#define RDIM 512
#define CDIM 64
#define NSBLK 16           // SDIM/128 blocks per r in kernel A

// ---------------- device scratch (no allocs allowed) ----------------
static __device__ float g_poolp[RDIM][NSBLK][64];        // per-(r, sblk) pool partials
static __device__ float g_msump[RDIM][NSBLK];            // per-(r, sblk) mask-sum partials
static __device__ float g_kv[(size_t)RDIM * SDIM * 16];  // [r][s][j]; j<8: k, j>=8: v
static __device__ float g_ovec[RDIM * CDIM];             // per r: o[h*8+ch]

__device__ __forceinline__ float sigm(float x) {
    float t = __expf(-x);
    return __fdividef(1.f, 1.f + t);
}
__device__ __forceinline__ void mma_bf16(float d[4],
    uint32_t a0, uint32_t a1, uint32_t a2, uint32_t a3,
    uint32_t b0, uint32_t b1)
{
    asm volatile(
        "mma.sync.aligned.m16n8k16.row.col.f32.bf16.bf16.f32 "
        "{%0,%1,%2,%3}, {%4,%5,%6,%7}, {%8,%9}, {%0,%1,%2,%3};"
        : "+f"(d[0]), "+f"(d[1]), "+f"(d[2]), "+f"(d[3])
        : "r"(a0), "r"(a1), "r"(a2), "r"(a3), "r"(b0), "r"(b1));
}
__device__ __forceinline__ uint32_t ld32s(const __nv_bfloat16* p) {
    return *(const uint32_t*)p;
}
__device__ __forceinline__ uint32_t pack_hi2(float x, float y) {
    __nv_bfloat16 hx = __float2bfloat16(x), hy = __float2bfloat16(y);
    return (uint32_t)__bfloat16_as_ushort(hx) | ((uint32_t)__bfloat16_as_ushort(hy) << 16);
}
__device__ __forceinline__ uint32_t pack_lo2(float x, float y) {
    __nv_bfloat16 hx = __float2bfloat16(x), hy = __float2bfloat16(y);
    __nv_bfloat16 lx = __float2bfloat16(x - __bfloat162float(hx));
    __nv_bfloat16 ly = __float2bfloat16(y - __bfloat162float(hy));
    return (uint32_t)__bfloat16_as_ushort(lx) | ((uint32_t)__bfloat16_as_ushort(ly) << 16);
}

// ========== kernel A: LN + masked pool + K/V via HMMA (unchanged) ==========
#define ASTR 72
__global__ void __launch_bounds__(256) k_pool_kv(
    const float* __restrict__ m, const float* __restrict__ mask,
    const float* __restrict__ ln_w, const float* __restrict__ ln_b,
    const float* __restrict__ wk, const float* __restrict__ wv)
{
    __shared__ __nv_bfloat16 s_ah[128 * ASTR];   // XN hi, row-major [row][c]
    __shared__ __nv_bfloat16 s_al[128 * ASTR];   // XN lo
    __shared__ __nv_bfloat16 s_bh[16 * ASTR];    // wkv^T hi: [j][c]
    __shared__ __nv_bfloat16 s_bl[16 * ASTR];
    __shared__ float s_pool[8][64];
    __shared__ float s_ms[8];

    const int r    = blockIdx.y;
    const int s0   = blockIdx.x * 128;
    const int tid  = threadIdx.x;
    const int lane = tid & 31;
    const int w    = tid >> 5;
    const int g    = lane >> 2;
    const int tig  = lane & 3;

    for (int idx = tid; idx < 1024; idx += 256) {
        int j = idx >> 6, c = idx & 63;
        float v = (j < 8) ? __ldg(&wk[c * 8 + j]) : __ldg(&wv[c * 8 + (j - 8)]);
        __nv_bfloat16 h = __float2bfloat16(v);
        s_bh[j * ASTR + c] = h;
        s_bl[j * ASTR + c] = __float2bfloat16(v - __bfloat162float(h));
    }

    const float lw0 = ln_w[lane], lw1 = ln_w[lane + 32];
    const float lb0 = ln_b[lane], lb1 = ln_b[lane + 32];
    float p0 = 0.f, p1 = 0.f, pm = 0.f;
    #pragma unroll
    for (int i = 0; i < 16; ++i) {
        const int row = w * 16 + i;
        const int s   = s0 + row;
        const float* mp = m + ((size_t)s * RDIM + r) * CDIM;
        float x0 = mp[lane];
        float x1 = mp[lane + 32];
        float mv = __ldg(&mask[s * RDIM + r]);

        float sum = x0 + x1;
        #pragma unroll
        for (int o = 16; o; o >>= 1) sum += __shfl_xor_sync(0xffffffffu, sum, o);
        float mu = sum * (1.f / 64.f);
        float d0 = x0 - mu, d1 = x1 - mu;
        float vv = d0 * d0 + d1 * d1;
        #pragma unroll
        for (int o = 16; o; o >>= 1) vv += __shfl_xor_sync(0xffffffffu, vv, o);
        float rstd = rsqrtf(vv * (1.f / 64.f) + 1e-5f);
        float xn0 = d0 * rstd * lw0 + lb0;
        float xn1 = d1 * rstd * lw1 + lb1;

        __nv_bfloat16 h0 = __float2bfloat16(xn0);
        __nv_bfloat16 h1 = __float2bfloat16(xn1);
        s_ah[row * ASTR + lane]      = h0;
        s_ah[row * ASTR + lane + 32] = h1;
        s_al[row * ASTR + lane]      = __float2bfloat16(xn0 - __bfloat162float(h0));
        s_al[row * ASTR + lane + 32] = __float2bfloat16(xn1 - __bfloat162float(h1));
        p0 += xn0 * mv;
        p1 += xn1 * mv;
        pm += mv;   // identical across lanes
    }
    s_pool[w][lane]      = p0;
    s_pool[w][lane + 32] = p1;
    if (lane == 0) s_ms[w] = pm;
    __syncthreads();

    if (tid < 64) {
        float a = 0.f;
        #pragma unroll
        for (int k = 0; k < 8; ++k) a += s_pool[k][tid];
        g_poolp[r][blockIdx.x][tid] = a;
    }
    if (tid == 0) {
        float a = 0.f;
        #pragma unroll
        for (int k = 0; k < 8; ++k) a += s_ms[k];
        g_msump[r][blockIdx.x] = a;
    }

    const int ar0 = w * 16 + g;
    float acc[2][4];
    #pragma unroll
    for (int nt = 0; nt < 2; ++nt)
        #pragma unroll
        for (int q = 0; q < 4; ++q) acc[nt][q] = 0.f;

    #pragma unroll
    for (int kk = 0; kk < 4; ++kk) {
        const int k0 = kk * 16 + tig * 2;
        uint32_t ah0 = ld32s(&s_ah[ar0 * ASTR + k0]);
        uint32_t ah1 = ld32s(&s_ah[(ar0 + 8) * ASTR + k0]);
        uint32_t ah2 = ld32s(&s_ah[ar0 * ASTR + k0 + 8]);
        uint32_t ah3 = ld32s(&s_ah[(ar0 + 8) * ASTR + k0 + 8]);
        uint32_t al0 = ld32s(&s_al[ar0 * ASTR + k0]);
        uint32_t al1 = ld32s(&s_al[(ar0 + 8) * ASTR + k0]);
        uint32_t al2 = ld32s(&s_al[ar0 * ASTR + k0 + 8]);
        uint32_t al3 = ld32s(&s_al[(ar0 + 8) * ASTR + k0 + 8]);
        #pragma unroll
        for (int nt = 0; nt < 2; ++nt) {
            const int n = nt * 8 + g;
            uint32_t bh0 = ld32s(&s_bh[n * ASTR + k0]);
            uint32_t bh1 = ld32s(&s_bh[n * ASTR + k0 + 8]);
            uint32_t bl0 = ld32s(&s_bl[n * ASTR + k0]);
            uint32_t bl1 = ld32s(&s_bl[n * ASTR + k0 + 8]);
            mma_bf16(acc[nt], ah0, ah1, ah2, ah3, bh0, bh1);
            mma_bf16(acc[nt], ah0, ah1, ah2, ah3, bl0, bl1);
            mma_bf16(acc[nt], al0, al1, al2, al3, bh0, bh1);
        }
    }
    #pragma unroll
    for (int nt = 0; nt < 2; ++nt) {
        const int j0 = nt * 8 + tig * 2;
        const int sr = s0 + ar0;
        float* p0 = g_kv + ((size_t)r * SDIM + sr) * 16 + j0;
        float* p1 = g_kv + ((size_t)r * SDIM + sr + 8) * 16 + j0;
        *(float2*)p0 = make_float2(acc[nt][0], acc[nt][1]);
        *(float2*)p1 = make_float2(acc[nt][2], acc[nt][3]);
    }
}

// ---------------- kernel B: pool reduce, q, softmax over S, o (unchanged) ----
__global__ void __launch_bounds__(256) k_attn(
    const float* __restrict__ mask, const float* __restrict__ wq)
{
    const int r   = blockIdx.x;
    const int tid = threadIdx.x;
    const int lane = tid & 31;
    const int h    = tid >> 5;

    __shared__ float s_p[64];
    __shared__ float s_red[256];
    __shared__ float s_minv;

    if (tid < 32) {
        float mm = (lane < NSBLK) ? g_msump[r][lane] : 0.f;
        #pragma unroll
        for (int o = 16; o; o >>= 1) mm += __shfl_xor_sync(0xffffffffu, mm, o);
        if (lane == 0) s_minv = __fdividef(1.f, mm + 1e-10f);
    }
    {
        int c = tid & 63, gp = tid >> 6;
        float a = 0.f;
        #pragma unroll
        for (int k = 0; k < 4; ++k) a += g_poolp[r][gp * 4 + k][c];
        s_red[tid] = a;
    }
    __syncthreads();
    if (tid < 64)
        s_p[tid] = (s_red[tid] + s_red[tid + 64] + s_red[tid + 128] + s_red[tid + 192]) * s_minv;
    __syncthreads();

    float q[8];
    float pc0 = s_p[lane], pc1 = s_p[lane + 32];
    #pragma unroll
    for (int j = 0; j < 8; ++j)
        q[j] = pc0 * wq[lane * 64 + h * 8 + j] + pc1 * wq[(lane + 32) * 64 + h * 8 + j];
    #pragma unroll
    for (int o = 16; o; o >>= 1) {
        #pragma unroll
        for (int j = 0; j < 8; ++j) q[j] += __shfl_xor_sync(0xffffffffu, q[j], o);
    }
    #pragma unroll
    for (int j = 0; j < 8; ++j) q[j] *= 0.35355339059327373f;

    const float LOG2E = 1.4426950408889634f;
    float M = -1e30f, L = 0.f;
    float acc[8];
    #pragma unroll
    for (int j = 0; j < 8; ++j) acc[j] = 0.f;

    for (int t = 0; t < SDIM / 32; ++t) {
        int s = t * 32 + lane;
        const float4* kv = (const float4*)(g_kv + ((size_t)r * SDIM + s) * 16);
        float4 k0 = kv[0], k1 = kv[1];
        float4 v0 = kv[2], v1 = kv[3];
        float mv = __ldg(&mask[s * RDIM + r]);
        float logit = q[0]*k0.x + q[1]*k0.y + q[2]*k0.z + q[3]*k0.w
                    + q[4]*k1.x + q[5]*k1.y + q[6]*k1.z + q[7]*k1.w
                    + 1e9f * (mv - 1.f);
        float nM = fmaxf(M, logit);
        float sc = exp2f((M - nM) * LOG2E);
        float p  = exp2f((logit - nM) * LOG2E);
        L = L * sc + p;
        acc[0] = acc[0]*sc + p*v0.x; acc[1] = acc[1]*sc + p*v0.y;
        acc[2] = acc[2]*sc + p*v0.z; acc[3] = acc[3]*sc + p*v0.w;
        acc[4] = acc[4]*sc + p*v1.x; acc[5] = acc[5]*sc + p*v1.y;
        acc[6] = acc[6]*sc + p*v1.z; acc[7] = acc[7]*sc + p*v1.w;
        M = nM;
    }
    float Mm = M;
    #pragma unroll
    for (int o = 16; o; o >>= 1) Mm = fmaxf(Mm, __shfl_xor_sync(0xffffffffu, Mm, o));
    float sc = exp2f((M - Mm) * LOG2E);
    L *= sc;
    #pragma unroll
    for (int j = 0; j < 8; ++j) acc[j] *= sc;
    #pragma unroll
    for (int o = 16; o; o >>= 1) {
        L += __shfl_xor_sync(0xffffffffu, L, o);
        #pragma unroll
        for (int j = 0; j < 8; ++j) acc[j] += __shfl_xor_sync(0xffffffffu, acc[j], o);
    }
    if (lane == 0) {
        float inv = 1.f / L;
        #pragma unroll
        for (int j = 0; j < 8; ++j) g_ovec[r * 64 + h * 8 + j] = acc[j] * inv;
    }
}

// ===== kernel C: HMMA 3-pass split; 4 chunks; warp-private phases =====
// All per-chunk state (A/G tile rows w*16..w*16+15) is owned by warp w:
// LN writes them, GEMM1 reads them, sigmoid overwrites them, GEMM2 reads
// them. Only the B tiles + biases are block-shared (staged once, read-only).
// => per-chunk barriers are __syncwarp(); one __syncthreads() after staging.
#define AS 72
#define BS 72
#define SMC_BYTES (2*128*AS*2 + 4*64*BS*2 + 2*64*4)   // 74240 B

__global__ void __launch_bounds__(256) k_out_mma(
    const float* __restrict__ m,
    const float* __restrict__ ln_w, const float* __restrict__ ln_b,
    const float* __restrict__ wg, const float* __restrict__ bg,
    const float* __restrict__ wo, const float* __restrict__ bo,
    float* __restrict__ out)
{
    extern __shared__ __align__(16) uint8_t smraw[];
    __nv_bfloat16* s_ah  = (__nv_bfloat16*)smraw;       // [128][AS] X hi / G hi
    __nv_bfloat16* s_al  = s_ah  + 128 * AS;            // [128][AS] X lo / G lo
    __nv_bfloat16* s_b1h = s_al  + 128 * AS;            // [64][BS]  wg^T hi
    __nv_bfloat16* s_b1l = s_b1h + 64 * BS;
    __nv_bfloat16* s_b2h = s_b1l + 64 * BS;             // [64][BS]  (ov.*wo)^T hi
    __nv_bfloat16* s_b2l = s_b2h + 64 * BS;
    float*         s_bg  = (float*)(s_b2l + 64 * BS);
    float*         s_bo  = s_bg + 64;

    const int r     = blockIdx.y;
    const int sbase = blockIdx.x * 512;    // quarter of S
    const int tid   = threadIdx.x;
    const int lane  = tid & 31;
    const int w     = tid >> 5;
    const int g     = lane >> 2;
    const int tig   = lane & 3;

    // ---- stage B1 = wg^T and B2 = (ov.*wo)^T once ----
    const float* ov = g_ovec + r * 64;
    for (int idx = tid; idx < 4096; idx += 256) {
        int c = idx >> 6, j = idx & 63;            // wg[c][j]
        float x = __ldg(&wg[idx]);
        __nv_bfloat16 h1 = __float2bfloat16(x);
        s_b1h[j * BS + c] = h1;
        s_b1l[j * BS + c] = __float2bfloat16(x - __bfloat162float(h1));

        int jj = c, cc = j;                        // wo[jj][cc]
        float y = __ldg(&ov[jj]) * __ldg(&wo[idx]);
        __nv_bfloat16 h2 = __float2bfloat16(y);
        s_b2h[cc * BS + jj] = h2;
        s_b2l[cc * BS + jj] = __float2bfloat16(y - __bfloat162float(h2));
    }
    if (tid < 64) { s_bg[tid] = bg[tid]; s_bo[tid] = bo[tid]; }
    __syncthreads();   // B tiles + biases visible to all warps; warps free-run after

    const float lw0 = ln_w[lane], lw1 = ln_w[lane + 32];
    const float lb0 = ln_b[lane], lb1 = ln_b[lane + 32];
    const int ar0 = w * 16 + g;

    for (int chunk = 0; chunk < 4; ++chunk) {
        const int s0 = sbase + chunk * 128;

        // LayerNorm: warp per row (16 rows/warp) — warp-private rows
        #pragma unroll
        for (int i = 0; i < 16; ++i) {
            const int row = w * 16 + i;
            const int s   = s0 + row;
            const float* mp = m + ((size_t)s * RDIM + r) * CDIM;
            float x0 = mp[lane];
            float x1 = mp[lane + 32];
            float sum = x0 + x1;
            #pragma unroll
            for (int o = 16; o; o >>= 1) sum += __shfl_xor_sync(0xffffffffu, sum, o);
            float mu = sum * (1.f / 64.f);
            float d0 = x0 - mu, d1 = x1 - mu;
            float vv = d0 * d0 + d1 * d1;
            #pragma unroll
            for (int o = 16; o; o >>= 1) vv += __shfl_xor_sync(0xffffffffu, vv, o);
            float rstd = rsqrtf(vv * (1.f / 64.f) + 1e-5f);
            float xn0 = d0 * rstd * lw0 + lb0;
            float xn1 = d1 * rstd * lw1 + lb1;
            __nv_bfloat16 h0 = __float2bfloat16(xn0);
            __nv_bfloat16 h1 = __float2bfloat16(xn1);
            s_ah[row * AS + lane]      = h0;
            s_ah[row * AS + lane + 32] = h1;
            s_al[row * AS + lane]      = __float2bfloat16(xn0 - __bfloat162float(h0));
            s_al[row * AS + lane + 32] = __float2bfloat16(xn1 - __bfloat162float(h1));
        }
        __syncwarp();

        // GEMM1: pre = XN @ wg
        float acc[8][4];
        #pragma unroll
        for (int nt = 0; nt < 8; ++nt)
            #pragma unroll
            for (int q = 0; q < 4; ++q) acc[nt][q] = 0.f;

        #pragma unroll
        for (int kk = 0; kk < 4; ++kk) {
            const int k0 = kk * 16 + tig * 2;
            uint32_t ah0 = ld32s(&s_ah[ar0 * AS + k0]);
            uint32_t ah1 = ld32s(&s_ah[(ar0 + 8) * AS + k0]);
            uint32_t ah2 = ld32s(&s_ah[ar0 * AS + k0 + 8]);
            uint32_t ah3 = ld32s(&s_ah[(ar0 + 8) * AS + k0 + 8]);
            uint32_t al0 = ld32s(&s_al[ar0 * AS + k0]);
            uint32_t al1 = ld32s(&s_al[(ar0 + 8) * AS + k0]);
            uint32_t al2 = ld32s(&s_al[ar0 * AS + k0 + 8]);
            uint32_t al3 = ld32s(&s_al[(ar0 + 8) * AS + k0 + 8]);
            #pragma unroll
            for (int nt = 0; nt < 8; ++nt) {
                const int n = nt * 8 + g;
                uint32_t bh0 = ld32s(&s_b1h[n * BS + k0]);
                uint32_t bh1 = ld32s(&s_b1h[n * BS + k0 + 8]);
                uint32_t bl0 = ld32s(&s_b1l[n * BS + k0]);
                uint32_t bl1 = ld32s(&s_b1l[n * BS + k0 + 8]);
                mma_bf16(acc[nt], ah0, ah1, ah2, ah3, bh0, bh1);
                mma_bf16(acc[nt], ah0, ah1, ah2, ah3, bl0, bl1);
                mma_bf16(acc[nt], al0, al1, al2, al3, bh0, bh1);
            }
        }
        __syncwarp();   // warp's GEMM1 reads of its A rows complete

        // epilogue 1: G = sigmoid(pre + bg) -> overwrite this warp's A rows
        #pragma unroll
        for (int nt = 0; nt < 8; ++nt) {
            const int col = nt * 8 + tig * 2;
            float v0 = sigm(acc[nt][0] + s_bg[col]);
            float v1 = sigm(acc[nt][1] + s_bg[col + 1]);
            float v2 = sigm(acc[nt][2] + s_bg[col]);
            float v3 = sigm(acc[nt][3] + s_bg[col + 1]);
            *(uint32_t*)&s_ah[ar0 * AS + col]       = pack_hi2(v0, v1);
            *(uint32_t*)&s_al[ar0 * AS + col]       = pack_lo2(v0, v1);
            *(uint32_t*)&s_ah[(ar0 + 8) * AS + col] = pack_hi2(v2, v3);
            *(uint32_t*)&s_al[(ar0 + 8) * AS + col] = pack_lo2(v2, v3);
        }
        __syncwarp();

        // GEMM2: out = G @ (ov.*wo) + bo
        float acc2[8][4];
        #pragma unroll
        for (int nt = 0; nt < 8; ++nt)
            #pragma unroll
            for (int q = 0; q < 4; ++q) acc2[nt][q] = 0.f;

        #pragma unroll
        for (int kk = 0; kk < 4; ++kk) {
            const int k0 = kk * 16 + tig * 2;
            uint32_t ah0 = ld32s(&s_ah[ar0 * AS + k0]);
            uint32_t ah1 = ld32s(&s_ah[(ar0 + 8) * AS + k0]);
            uint32_t ah2 = ld32s(&s_ah[ar0 * AS + k0 + 8]);
            uint32_t ah3 = ld32s(&s_ah[(ar0 + 8) * AS + k0 + 8]);
            uint32_t al0 = ld32s(&s_al[ar0 * AS + k0]);
            uint32_t al1 = ld32s(&s_al[(ar0 + 8) * AS + k0]);
            uint32_t al2 = ld32s(&s_al[ar0 * AS + k0 + 8]);
            uint32_t al3 = ld32s(&s_al[(ar0 + 8) * AS + k0 + 8]);
            #pragma unroll
            for (int nt = 0; nt < 8; ++nt) {
                const int n = nt * 8 + g;
                uint32_t bh0 = ld32s(&s_b2h[n * BS + k0]);
                uint32_t bh1 = ld32s(&s_b2h[n * BS + k0 + 8]);
                uint32_t bl0 = ld32s(&s_b2l[n * BS + k0]);
                uint32_t bl1 = ld32s(&s_b2l[n * BS + k0 + 8]);
                mma_bf16(acc2[nt], ah0, ah1, ah2, ah3, bh0, bh1);
                mma_bf16(acc2[nt], ah0, ah1, ah2, ah3, bl0, bl1);
                mma_bf16(acc2[nt], al0, al1, al2, al3, bh0, bh1);
            }
        }

        // final store: + bo
        {
            const int row0 = s0 + ar0;
            float* op0 = out + ((size_t)row0 * RDIM + r) * CDIM;
            float* op1 = out + ((size_t)(row0 + 8) * RDIM + r) * CDIM;
            #pragma unroll
            for (int nt = 0; nt < 8; ++nt) {
                const int col = nt * 8 + tig * 2;
                float b0 = s_bo[col], b1 = s_bo[col + 1];
                *(float2*)(op0 + col) = make_float2(acc2[nt][0] + b0, acc2[nt][1] + b1);
                *(float2*)(op1 + col) = make_float2(acc2[nt][2] + b0, acc2[nt][3] + b1);
            }
        }
        __syncwarp();   // warp's GEMM2 reads done before its next-chunk LN overwrites
    }
}

// ---------------------------------------------------------------------
extern "C" void kernel_launch(void* const* d_in, const int* in_sizes, int n_in,
                              void* d_out, int out_size) {
    const float* m    = (const float*)d_in[0];
    const float* mask = (const float*)d_in[1];
    const float* ln_w = (const float*)d_in[2];
    const float* ln_b = (const float*)d_in[3];
    const float* wq   = (const float*)d_in[4];
    const float* wk   = (const float*)d_in[5];
    const float* wv   = (const float*)d_in[6];
    const float* wg   = (const float*)d_in[7];
    const float* bg   = (const float*)d_in[8];
    const float* wo   = (const float*)d_in[9];
    const float* bo   = (const float*)d_in[10];
    float* out = (float*)d_out;

    cudaFuncSetAttribute(k_out_mma, cudaFuncAttributeMaxDynamicSharedMemorySize, SMC_BYTES);

    dim3 gA(NSBLK, RDIM);
    k_pool_kv<<<gA, 256>>>(m, mask, ln_w, ln_b, wk, wv);
    k_attn<<<RDIM, 256>>>(mask, wq);
    dim3 gC(4, RDIM);
    k_out_mma<<<gC, 256, SMC_BYTES>>>(m, ln_w, ln_b, wg, bg, wo, bo, out);
}

// round 14
// speedup vs baseline: 1.4084x; 1.1961x over previous
#include <cuda_runtime.h>
#include <cuda_bf16.h>
#include <cuda_fp16.h>
#include <math.h>
#include <stdint.h>

// Problem shape (fixed by setup_inputs)
#define SDIM 2048
#define RDIM 512
#define CDIM 64
#define NSBLK 16           // SDIM/128 blocks per r in kernel A

// ---------------- device scratch (no allocs allowed) ----------------
static __device__ float g_poolp[RDIM][NSBLK][64];        // per-(r, sblk) pool partials
static __device__ float g_msump[RDIM][NSBLK];            // per-(r, sblk) mask-sum partials
static __device__ float g_kv[(size_t)RDIM * SDIM * 16];  // [r][s][j]; j<8: k, j>=8: v
static __device__ float g_ovec[RDIM * CDIM];             // per r: o[h*8+ch]

__device__ __forceinline__ float sigm(float x) {
    float t = __expf(-x);
    return __fdividef(1.f, 1.f + t);
}
__device__ __forceinline__ void mma_bf16(float d[4],
    uint32_t a0, uint32_t a1, uint32_t a2, uint32_t a3,
    uint32_t b0, uint32_t b1)
{
    asm volatile(
        "mma.sync.aligned.m16n8k16.row.col.f32.bf16.bf16.f32 "
        "{%0,%1,%2,%3}, {%4,%5,%6,%7}, {%8,%9}, {%0,%1,%2,%3};"
        : "+f"(d[0]), "+f"(d[1]), "+f"(d[2]), "+f"(d[3])
        : "r"(a0), "r"(a1), "r"(a2), "r"(a3), "r"(b0), "r"(b1));
}
__device__ __forceinline__ void mma_f16(float d[4],
    uint32_t a0, uint32_t a1, uint32_t a2, uint32_t a3,
    uint32_t b0, uint32_t b1)
{
    asm volatile(
        "mma.sync.aligned.m16n8k16.row.col.f32.f16.f16.f32 "
        "{%0,%1,%2,%3}, {%4,%5,%6,%7}, {%8,%9}, {%0,%1,%2,%3};"
        : "+f"(d[0]), "+f"(d[1]), "+f"(d[2]), "+f"(d[3])
        : "r"(a0), "r"(a1), "r"(a2), "r"(a3), "r"(b0), "r"(b1));
}
__device__ __forceinline__ uint32_t ld32s(const void* p) {
    return *(const uint32_t*)p;
}
__device__ __forceinline__ uint32_t pack_h2(float x, float y) {
    __half2 h = __floats2half2_rn(x, y);
    return *(uint32_t*)&h;
}

// ========== kernel A: LN + masked pool + K/V via HMMA (unchanged) ==========
#define ASTR 72
__global__ void __launch_bounds__(256) k_pool_kv(
    const float* __restrict__ m, const float* __restrict__ mask,
    const float* __restrict__ ln_w, const float* __restrict__ ln_b,
    const float* __restrict__ wk, const float* __restrict__ wv)
{
    __shared__ __nv_bfloat16 s_ah[128 * ASTR];   // XN hi, row-major [row][c]
    __shared__ __nv_bfloat16 s_al[128 * ASTR];   // XN lo
    __shared__ __nv_bfloat16 s_bh[16 * ASTR];    // wkv^T hi: [j][c]
    __shared__ __nv_bfloat16 s_bl[16 * ASTR];
    __shared__ float s_pool[8][64];
    __shared__ float s_ms[8];

    const int r    = blockIdx.y;
    const int s0   = blockIdx.x * 128;
    const int tid  = threadIdx.x;
    const int lane = tid & 31;
    const int w    = tid >> 5;
    const int g    = lane >> 2;
    const int tig  = lane & 3;

    for (int idx = tid; idx < 1024; idx += 256) {
        int j = idx >> 6, c = idx & 63;
        float v = (j < 8) ? __ldg(&wk[c * 8 + j]) : __ldg(&wv[c * 8 + (j - 8)]);
        __nv_bfloat16 h = __float2bfloat16(v);
        s_bh[j * ASTR + c] = h;
        s_bl[j * ASTR + c] = __float2bfloat16(v - __bfloat162float(h));
    }

    const float lw0 = ln_w[lane], lw1 = ln_w[lane + 32];
    const float lb0 = ln_b[lane], lb1 = ln_b[lane + 32];
    float p0 = 0.f, p1 = 0.f, pm = 0.f;
    #pragma unroll
    for (int i = 0; i < 16; ++i) {
        const int row = w * 16 + i;
        const int s   = s0 + row;
        const float* mp = m + ((size_t)s * RDIM + r) * CDIM;
        float x0 = mp[lane];
        float x1 = mp[lane + 32];
        float mv = __ldg(&mask[s * RDIM + r]);

        float sum = x0 + x1;
        #pragma unroll
        for (int o = 16; o; o >>= 1) sum += __shfl_xor_sync(0xffffffffu, sum, o);
        float mu = sum * (1.f / 64.f);
        float d0 = x0 - mu, d1 = x1 - mu;
        float vv = d0 * d0 + d1 * d1;
        #pragma unroll
        for (int o = 16; o; o >>= 1) vv += __shfl_xor_sync(0xffffffffu, vv, o);
        float rstd = rsqrtf(vv * (1.f / 64.f) + 1e-5f);
        float xn0 = d0 * rstd * lw0 + lb0;
        float xn1 = d1 * rstd * lw1 + lb1;

        __nv_bfloat16 h0 = __float2bfloat16(xn0);
        __nv_bfloat16 h1 = __float2bfloat16(xn1);
        s_ah[row * ASTR + lane]      = h0;
        s_ah[row * ASTR + lane + 32] = h1;
        s_al[row * ASTR + lane]      = __float2bfloat16(xn0 - __bfloat162float(h0));
        s_al[row * ASTR + lane + 32] = __float2bfloat16(xn1 - __bfloat162float(h1));
        p0 += xn0 * mv;
        p1 += xn1 * mv;
        pm += mv;   // identical across lanes
    }
    s_pool[w][lane]      = p0;
    s_pool[w][lane + 32] = p1;
    if (lane == 0) s_ms[w] = pm;
    __syncthreads();

    if (tid < 64) {
        float a = 0.f;
        #pragma unroll
        for (int k = 0; k < 8; ++k) a += s_pool[k][tid];
        g_poolp[r][blockIdx.x][tid] = a;
    }
    if (tid == 0) {
        float a = 0.f;
        #pragma unroll
        for (int k = 0; k < 8; ++k) a += s_ms[k];
        g_msump[r][blockIdx.x] = a;
    }

    const int ar0 = w * 16 + g;
    float acc[2][4];
    #pragma unroll
    for (int nt = 0; nt < 2; ++nt)
        #pragma unroll
        for (int q = 0; q < 4; ++q) acc[nt][q] = 0.f;

    #pragma unroll
    for (int kk = 0; kk < 4; ++kk) {
        const int k0 = kk * 16 + tig * 2;
        uint32_t ah0 = ld32s(&s_ah[ar0 * ASTR + k0]);
        uint32_t ah1 = ld32s(&s_ah[(ar0 + 8) * ASTR + k0]);
        uint32_t ah2 = ld32s(&s_ah[ar0 * ASTR + k0 + 8]);
        uint32_t ah3 = ld32s(&s_ah[(ar0 + 8) * ASTR + k0 + 8]);
        uint32_t al0 = ld32s(&s_al[ar0 * ASTR + k0]);
        uint32_t al1 = ld32s(&s_al[(ar0 + 8) * ASTR + k0]);
        uint32_t al2 = ld32s(&s_al[ar0 * ASTR + k0 + 8]);
        uint32_t al3 = ld32s(&s_al[(ar0 + 8) * ASTR + k0 + 8]);
        #pragma unroll
        for (int nt = 0; nt < 2; ++nt) {
            const int n = nt * 8 + g;
            uint32_t bh0 = ld32s(&s_bh[n * ASTR + k0]);
            uint32_t bh1 = ld32s(&s_bh[n * ASTR + k0 + 8]);
            uint32_t bl0 = ld32s(&s_bl[n * ASTR + k0]);
            uint32_t bl1 = ld32s(&s_bl[n * ASTR + k0 + 8]);
            mma_bf16(acc[nt], ah0, ah1, ah2, ah3, bh0, bh1);
            mma_bf16(acc[nt], ah0, ah1, ah2, ah3, bl0, bl1);
            mma_bf16(acc[nt], al0, al1, al2, al3, bh0, bh1);
        }
    }
    #pragma unroll
    for (int nt = 0; nt < 2; ++nt) {
        const int j0 = nt * 8 + tig * 2;
        const int sr = s0 + ar0;
        float* p0 = g_kv + ((size_t)r * SDIM + sr) * 16 + j0;
        float* p1 = g_kv + ((size_t)r * SDIM + sr + 8) * 16 + j0;
        *(float2*)p0 = make_float2(acc[nt][0], acc[nt][1]);
        *(float2*)p1 = make_float2(acc[nt][2], acc[nt][3]);
    }
}

// ---------------- kernel B: pool reduce, q, softmax over S, o (unchanged) ----
__global__ void __launch_bounds__(256) k_attn(
    const float* __restrict__ mask, const float* __restrict__ wq)
{
    const int r   = blockIdx.x;
    const int tid = threadIdx.x;
    const int lane = tid & 31;
    const int h    = tid >> 5;

    __shared__ float s_p[64];
    __shared__ float s_red[256];
    __shared__ float s_minv;

    if (tid < 32) {
        float mm = (lane < NSBLK) ? g_msump[r][lane] : 0.f;
        #pragma unroll
        for (int o = 16; o; o >>= 1) mm += __shfl_xor_sync(0xffffffffu, mm, o);
        if (lane == 0) s_minv = __fdividef(1.f, mm + 1e-10f);
    }
    {
        int c = tid & 63, gp = tid >> 6;
        float a = 0.f;
        #pragma unroll
        for (int k = 0; k < 4; ++k) a += g_poolp[r][gp * 4 + k][c];
        s_red[tid] = a;
    }
    __syncthreads();
    if (tid < 64)
        s_p[tid] = (s_red[tid] + s_red[tid + 64] + s_red[tid + 128] + s_red[tid + 192]) * s_minv;
    __syncthreads();

    float q[8];
    float pc0 = s_p[lane], pc1 = s_p[lane + 32];
    #pragma unroll
    for (int j = 0; j < 8; ++j)
        q[j] = pc0 * wq[lane * 64 + h * 8 + j] + pc1 * wq[(lane + 32) * 64 + h * 8 + j];
    #pragma unroll
    for (int o = 16; o; o >>= 1) {
        #pragma unroll
        for (int j = 0; j < 8; ++j) q[j] += __shfl_xor_sync(0xffffffffu, q[j], o);
    }
    #pragma unroll
    for (int j = 0; j < 8; ++j) q[j] *= 0.35355339059327373f;

    const float LOG2E = 1.4426950408889634f;
    float M = -1e30f, L = 0.f;
    float acc[8];
    #pragma unroll
    for (int j = 0; j < 8; ++j) acc[j] = 0.f;

    for (int t = 0; t < SDIM / 32; ++t) {
        int s = t * 32 + lane;
        const float4* kv = (const float4*)(g_kv + ((size_t)r * SDIM + s) * 16);
        float4 k0 = kv[0], k1 = kv[1];
        float4 v0 = kv[2], v1 = kv[3];
        float mv = __ldg(&mask[s * RDIM + r]);
        float logit = q[0]*k0.x + q[1]*k0.y + q[2]*k0.z + q[3]*k0.w
                    + q[4]*k1.x + q[5]*k1.y + q[6]*k1.z + q[7]*k1.w
                    + 1e9f * (mv - 1.f);
        float nM = fmaxf(M, logit);
        float sc = exp2f((M - nM) * LOG2E);
        float p  = exp2f((logit - nM) * LOG2E);
        L = L * sc + p;
        acc[0] = acc[0]*sc + p*v0.x; acc[1] = acc[1]*sc + p*v0.y;
        acc[2] = acc[2]*sc + p*v0.z; acc[3] = acc[3]*sc + p*v0.w;
        acc[4] = acc[4]*sc + p*v1.x; acc[5] = acc[5]*sc + p*v1.y;
        acc[6] = acc[6]*sc + p*v1.z; acc[7] = acc[7]*sc + p*v1.w;
        M = nM;
    }
    float Mm = M;
    #pragma unroll
    for (int o = 16; o; o >>= 1) Mm = fmaxf(Mm, __shfl_xor_sync(0xffffffffu, Mm, o));
    float sc = exp2f((M - Mm) * LOG2E);
    L *= sc;
    #pragma unroll
    for (int j = 0; j < 8; ++j) acc[j] *= sc;
    #pragma unroll
    for (int o = 16; o; o >>= 1) {
        L += __shfl_xor_sync(0xffffffffu, L, o);
        #pragma unroll
        for (int j = 0; j < 8; ++j) acc[j] += __shfl_xor_sync(0xffffffffu, acc[j], o);
    }
    if (lane == 0) {
        float inv = 1.f / L;
        #pragma unroll
        for (int j = 0; j < 8; ++j) g_ovec[r * 64 + h * 8 + j] = acc[j] * inv;
    }
}

// ===== kernel C: fp16 single-pass HMMA; 4 chunks; warp-private phases =====
// fp16 (11 mantissa bits) single-pass replaces bf16 3-pass: 3x fewer MMAs,
// half the fragment LDS, half the smem. fp32 accumulate throughout.
#define AS 72
#define BS 72
#define SMC_BYTES (128*AS*2 + 2*64*BS*2 + 2*64*4)   // 37376 B

__global__ void __launch_bounds__(256) k_out_mma(
    const float* __restrict__ m,
    const float* __restrict__ ln_w, const float* __restrict__ ln_b,
    const float* __restrict__ wg, const float* __restrict__ bg,
    const float* __restrict__ wo, const float* __restrict__ bo,
    float* __restrict__ out)
{
    extern __shared__ __align__(16) uint8_t smraw[];
    __half* s_a  = (__half*)smraw;         // [128][AS] XN / later G (fp16)
    __half* s_b1 = s_a  + 128 * AS;        // [64][BS]  wg^T (fp16)
    __half* s_b2 = s_b1 + 64 * BS;         // [64][BS]  (ov.*wo)^T (fp16)
    float*  s_bg = (float*)(s_b2 + 64 * BS);
    float*  s_bo = s_bg + 64;

    const int r     = blockIdx.y;
    const int sbase = blockIdx.x * 512;    // quarter of S
    const int tid   = threadIdx.x;
    const int lane  = tid & 31;
    const int w     = tid >> 5;
    const int g     = lane >> 2;
    const int tig   = lane & 3;

    // ---- stage B1 = wg^T and B2 = (ov.*wo)^T once (fp16) ----
    const float* ov = g_ovec + r * 64;
    for (int idx = tid; idx < 4096; idx += 256) {
        int c = idx >> 6, j = idx & 63;            // wg[c][j]
        s_b1[j * BS + c] = __float2half_rn(__ldg(&wg[idx]));
        int jj = c, cc = j;                        // wo[jj][cc]
        s_b2[cc * BS + jj] = __float2half_rn(__ldg(&ov[jj]) * __ldg(&wo[idx]));
    }
    if (tid < 64) { s_bg[tid] = bg[tid]; s_bo[tid] = bo[tid]; }
    __syncthreads();   // B tiles + biases visible; warps free-run after

    const float lw0 = ln_w[lane], lw1 = ln_w[lane + 32];
    const float lb0 = ln_b[lane], lb1 = ln_b[lane + 32];
    const int ar0 = w * 16 + g;

    for (int chunk = 0; chunk < 4; ++chunk) {
        const int s0 = sbase + chunk * 128;

        // LayerNorm: warp per row (16 rows/warp) — warp-private rows
        #pragma unroll
        for (int i = 0; i < 16; ++i) {
            const int row = w * 16 + i;
            const int s   = s0 + row;
            const float* mp = m + ((size_t)s * RDIM + r) * CDIM;
            float x0 = mp[lane];
            float x1 = mp[lane + 32];
            float sum = x0 + x1;
            #pragma unroll
            for (int o = 16; o; o >>= 1) sum += __shfl_xor_sync(0xffffffffu, sum, o);
            float mu = sum * (1.f / 64.f);
            float d0 = x0 - mu, d1 = x1 - mu;
            float vv = d0 * d0 + d1 * d1;
            #pragma unroll
            for (int o = 16; o; o >>= 1) vv += __shfl_xor_sync(0xffffffffu, vv, o);
            float rstd = rsqrtf(vv * (1.f / 64.f) + 1e-5f);
            s_a[row * AS + lane]      = __float2half_rn(d0 * rstd * lw0 + lb0);
            s_a[row * AS + lane + 32] = __float2half_rn(d1 * rstd * lw1 + lb1);
        }
        __syncwarp();

        // GEMM1: pre = XN @ wg  (fp16 single-pass)
        float acc[8][4];
        #pragma unroll
        for (int nt = 0; nt < 8; ++nt)
            #pragma unroll
            for (int q = 0; q < 4; ++q) acc[nt][q] = 0.f;

        #pragma unroll
        for (int kk = 0; kk < 4; ++kk) {
            const int k0 = kk * 16 + tig * 2;
            uint32_t a0 = ld32s(&s_a[ar0 * AS + k0]);
            uint32_t a1 = ld32s(&s_a[(ar0 + 8) * AS + k0]);
            uint32_t a2 = ld32s(&s_a[ar0 * AS + k0 + 8]);
            uint32_t a3 = ld32s(&s_a[(ar0 + 8) * AS + k0 + 8]);
            #pragma unroll
            for (int nt = 0; nt < 8; ++nt) {
                const int n = nt * 8 + g;
                uint32_t b0 = ld32s(&s_b1[n * BS + k0]);
                uint32_t b1 = ld32s(&s_b1[n * BS + k0 + 8]);
                mma_f16(acc[nt], a0, a1, a2, a3, b0, b1);
            }
        }
        __syncwarp();   // warp's GEMM1 reads of its A rows complete

        // epilogue 1: G = sigmoid(pre + bg) -> overwrite this warp's A rows
        #pragma unroll
        for (int nt = 0; nt < 8; ++nt) {
            const int col = nt * 8 + tig * 2;
            float v0 = sigm(acc[nt][0] + s_bg[col]);
            float v1 = sigm(acc[nt][1] + s_bg[col + 1]);
            float v2 = sigm(acc[nt][2] + s_bg[col]);
            float v3 = sigm(acc[nt][3] + s_bg[col + 1]);
            *(uint32_t*)&s_a[ar0 * AS + col]       = pack_h2(v0, v1);
            *(uint32_t*)&s_a[(ar0 + 8) * AS + col] = pack_h2(v2, v3);
        }
        __syncwarp();

        // GEMM2: out = G @ (ov.*wo) + bo
        float acc2[8][4];
        #pragma unroll
        for (int nt = 0; nt < 8; ++nt)
            #pragma unroll
            for (int q = 0; q < 4; ++q) acc2[nt][q] = 0.f;

        #pragma unroll
        for (int kk = 0; kk < 4; ++kk) {
            const int k0 = kk * 16 + tig * 2;
            uint32_t a0 = ld32s(&s_a[ar0 * AS + k0]);
            uint32_t a1 = ld32s(&s_a[(ar0 + 8) * AS + k0]);
            uint32_t a2 = ld32s(&s_a[ar0 * AS + k0 + 8]);
            uint32_t a3 = ld32s(&s_a[(ar0 + 8) * AS + k0 + 8]);
            #pragma unroll
            for (int nt = 0; nt < 8; ++nt) {
                const int n = nt * 8 + g;
                uint32_t b0 = ld32s(&s_b2[n * BS + k0]);
                uint32_t b1 = ld32s(&s_b2[n * BS + k0 + 8]);
                mma_f16(acc2[nt], a0, a1, a2, a3, b0, b1);
            }
        }

        // final store: + bo
        {
            const int row0 = s0 + ar0;
            float* op0 = out + ((size_t)row0 * RDIM + r) * CDIM;
            float* op1 = out + ((size_t)(row0 + 8) * RDIM + r) * CDIM;
            #pragma unroll
            for (int nt = 0; nt < 8; ++nt) {
                const int col = nt * 8 + tig * 2;
                float b0 = s_bo[col], b1 = s_bo[col + 1];
                *(float2*)(op0 + col) = make_float2(acc2[nt][0] + b0, acc2[nt][1] + b1);
                *(float2*)(op1 + col) = make_float2(acc2[nt][2] + b0, acc2[nt][3] + b1);
            }
        }
        __syncwarp();   // warp's GEMM2 reads done before next-chunk LN overwrites
    }
}

// ---------------------------------------------------------------------
extern "C" void kernel_launch(void* const* d_in, const int* in_sizes, int n_in,
                              void* d_out, int out_size) {
    const float* m    = (const float*)d_in[0];
    const float* mask = (const float*)d_in[1];
    const float* ln_w = (const float*)d_in[2];
    const float* ln_b = (const float*)d_in[3];
    const float* wq   = (const float*)d_in[4];
    const float* wk   = (const float*)d_in[5];
    const float* wv   = (const float*)d_in[6];
    const float* wg   = (const float*)d_in[7];
    const float* bg   = (const float*)d_in[8];
    const float* wo   = (const float*)d_in[9];
    const float* bo   = (const float*)d_in[10];
    float* out = (float*)d_out;

    cudaFuncSetAttribute(k_out_mma, cudaFuncAttributeMaxDynamicSharedMemorySize, SMC_BYTES);

    dim3 gA(NSBLK, RDIM);
    k_pool_kv<<<gA, 256>>>(m, mask, ln_w, ln_b, wk, wv);
    k_attn<<<RDIM, 256>>>(mask, wq);
    dim3 gC(4, RDIM);
    k_out_mma<<<gC, 256, SMC_BYTES>>>(m, ln_w, ln_b, wg, bg, wo, bo, out);
}

// round 15
// speedup vs baseline: 1.4419x; 1.0238x over previous
#include <cuda_runtime.h>
#include <cuda_bf16.h>
#include <cuda_fp16.h>
#include <math.h>
#include <stdint.h>

// Problem shape (fixed by setup_inputs)
#define SDIM 2048
#define RDIM 512
#define CDIM 64
#define NSBLK 16           // SDIM/128 blocks per r in kernel A

// ---------------- device scratch (no allocs allowed) ----------------
static __device__ float  g_poolp[RDIM][NSBLK][64];        // per-(r, sblk) pool partials
static __device__ float  g_msump[RDIM][NSBLK];            // per-(r, sblk) mask-sum partials
static __device__ float  g_kv[(size_t)RDIM * SDIM * 16];  // [r][s][j]; j<8: k, j>=8: v
static __device__ float  g_ovec[RDIM * CDIM];             // per r: o[h*8+ch]
static __device__ __half g_xn[(size_t)RDIM * SDIM * 64];  // [r][s][c] LayerNorm(x) in fp16

__device__ __forceinline__ float sigm(float x) {
    float t = __expf(-x);
    return __fdividef(1.f, 1.f + t);
}
__device__ __forceinline__ void mma_bf16(float d[4],
    uint32_t a0, uint32_t a1, uint32_t a2, uint32_t a3,
    uint32_t b0, uint32_t b1)
{
    asm volatile(
        "mma.sync.aligned.m16n8k16.row.col.f32.bf16.bf16.f32 "
        "{%0,%1,%2,%3}, {%4,%5,%6,%7}, {%8,%9}, {%0,%1,%2,%3};"
        : "+f"(d[0]), "+f"(d[1]), "+f"(d[2]), "+f"(d[3])
        : "r"(a0), "r"(a1), "r"(a2), "r"(a3), "r"(b0), "r"(b1));
}
__device__ __forceinline__ void mma_f16(float d[4],
    uint32_t a0, uint32_t a1, uint32_t a2, uint32_t a3,
    uint32_t b0, uint32_t b1)
{
    asm volatile(
        "mma.sync.aligned.m16n8k16.row.col.f32.f16.f16.f32 "
        "{%0,%1,%2,%3}, {%4,%5,%6,%7}, {%8,%9}, {%0,%1,%2,%3};"
        : "+f"(d[0]), "+f"(d[1]), "+f"(d[2]), "+f"(d[3])
        : "r"(a0), "r"(a1), "r"(a2), "r"(a3), "r"(b0), "r"(b1));
}
__device__ __forceinline__ uint32_t ld32s(const void* p) {
    return *(const uint32_t*)p;
}
__device__ __forceinline__ uint32_t pack_h2(float x, float y) {
    __half2 h = __floats2half2_rn(x, y);
    return *(uint32_t*)&h;
}

// ========== kernel A: LN + masked pool + K/V via HMMA + XN(fp16) export ==========
#define ASTR 72
__global__ void __launch_bounds__(256) k_pool_kv(
    const float* __restrict__ m, const float* __restrict__ mask,
    const float* __restrict__ ln_w, const float* __restrict__ ln_b,
    const float* __restrict__ wk, const float* __restrict__ wv)
{
    __shared__ __nv_bfloat16 s_ah[128 * ASTR];   // XN hi, row-major [row][c]
    __shared__ __nv_bfloat16 s_al[128 * ASTR];   // XN lo
    __shared__ __nv_bfloat16 s_bh[16 * ASTR];    // wkv^T hi: [j][c]
    __shared__ __nv_bfloat16 s_bl[16 * ASTR];
    __shared__ float s_pool[8][64];
    __shared__ float s_ms[8];

    const int r    = blockIdx.y;
    const int s0   = blockIdx.x * 128;
    const int tid  = threadIdx.x;
    const int lane = tid & 31;
    const int w    = tid >> 5;
    const int g    = lane >> 2;
    const int tig  = lane & 3;

    for (int idx = tid; idx < 1024; idx += 256) {
        int j = idx >> 6, c = idx & 63;
        float v = (j < 8) ? __ldg(&wk[c * 8 + j]) : __ldg(&wv[c * 8 + (j - 8)]);
        __nv_bfloat16 h = __float2bfloat16(v);
        s_bh[j * ASTR + c] = h;
        s_bl[j * ASTR + c] = __float2bfloat16(v - __bfloat162float(h));
    }

    const float lw0 = ln_w[lane], lw1 = ln_w[lane + 32];
    const float lb0 = ln_b[lane], lb1 = ln_b[lane + 32];
    float p0 = 0.f, p1 = 0.f, pm = 0.f;
    #pragma unroll
    for (int i = 0; i < 16; ++i) {
        const int row = w * 16 + i;
        const int s   = s0 + row;
        const float* mp = m + ((size_t)s * RDIM + r) * CDIM;
        float x0 = mp[lane];
        float x1 = mp[lane + 32];
        float mv = __ldg(&mask[s * RDIM + r]);

        float sum = x0 + x1;
        #pragma unroll
        for (int o = 16; o; o >>= 1) sum += __shfl_xor_sync(0xffffffffu, sum, o);
        float mu = sum * (1.f / 64.f);
        float d0 = x0 - mu, d1 = x1 - mu;
        float vv = d0 * d0 + d1 * d1;
        #pragma unroll
        for (int o = 16; o; o >>= 1) vv += __shfl_xor_sync(0xffffffffu, vv, o);
        float rstd = rsqrtf(vv * (1.f / 64.f) + 1e-5f);
        float xn0 = d0 * rstd * lw0 + lb0;
        float xn1 = d1 * rstd * lw1 + lb1;

        __nv_bfloat16 h0 = __float2bfloat16(xn0);
        __nv_bfloat16 h1 = __float2bfloat16(xn1);
        s_ah[row * ASTR + lane]      = h0;
        s_ah[row * ASTR + lane + 32] = h1;
        s_al[row * ASTR + lane]      = __float2bfloat16(xn0 - __bfloat162float(h0));
        s_al[row * ASTR + lane + 32] = __float2bfloat16(xn1 - __bfloat162float(h1));

        // export XN in fp16 for kernel C (identical to C's own __float2half_rn)
        __half* xp = g_xn + ((size_t)r * SDIM + s) * 64;
        xp[lane]      = __float2half_rn(xn0);
        xp[lane + 32] = __float2half_rn(xn1);

        p0 += xn0 * mv;
        p1 += xn1 * mv;
        pm += mv;   // identical across lanes
    }
    s_pool[w][lane]      = p0;
    s_pool[w][lane + 32] = p1;
    if (lane == 0) s_ms[w] = pm;
    __syncthreads();

    if (tid < 64) {
        float a = 0.f;
        #pragma unroll
        for (int k = 0; k < 8; ++k) a += s_pool[k][tid];
        g_poolp[r][blockIdx.x][tid] = a;
    }
    if (tid == 0) {
        float a = 0.f;
        #pragma unroll
        for (int k = 0; k < 8; ++k) a += s_ms[k];
        g_msump[r][blockIdx.x] = a;
    }

    const int ar0 = w * 16 + g;
    float acc[2][4];
    #pragma unroll
    for (int nt = 0; nt < 2; ++nt)
        #pragma unroll
        for (int q = 0; q < 4; ++q) acc[nt][q] = 0.f;

    #pragma unroll
    for (int kk = 0; kk < 4; ++kk) {
        const int k0 = kk * 16 + tig * 2;
        uint32_t ah0 = ld32s(&s_ah[ar0 * ASTR + k0]);
        uint32_t ah1 = ld32s(&s_ah[(ar0 + 8) * ASTR + k0]);
        uint32_t ah2 = ld32s(&s_ah[ar0 * ASTR + k0 + 8]);
        uint32_t ah3 = ld32s(&s_ah[(ar0 + 8) * ASTR + k0 + 8]);
        uint32_t al0 = ld32s(&s_al[ar0 * ASTR + k0]);
        uint32_t al1 = ld32s(&s_al[(ar0 + 8) * ASTR + k0]);
        uint32_t al2 = ld32s(&s_al[ar0 * ASTR + k0 + 8]);
        uint32_t al3 = ld32s(&s_al[(ar0 + 8) * ASTR + k0 + 8]);
        #pragma unroll
        for (int nt = 0; nt < 2; ++nt) {
            const int n = nt * 8 + g;
            uint32_t bh0 = ld32s(&s_bh[n * ASTR + k0]);
            uint32_t bh1 = ld32s(&s_bh[n * ASTR + k0 + 8]);
            uint32_t bl0 = ld32s(&s_bl[n * ASTR + k0]);
            uint32_t bl1 = ld32s(&s_bl[n * ASTR + k0 + 8]);
            mma_bf16(acc[nt], ah0, ah1, ah2, ah3, bh0, bh1);
            mma_bf16(acc[nt], ah0, ah1, ah2, ah3, bl0, bl1);
            mma_bf16(acc[nt], al0, al1, al2, al3, bh0, bh1);
        }
    }
    #pragma unroll
    for (int nt = 0; nt < 2; ++nt) {
        const int j0 = nt * 8 + tig * 2;
        const int sr = s0 + ar0;
        float* p0 = g_kv + ((size_t)r * SDIM + sr) * 16 + j0;
        float* p1 = g_kv + ((size_t)r * SDIM + sr + 8) * 16 + j0;
        *(float2*)p0 = make_float2(acc[nt][0], acc[nt][1]);
        *(float2*)p1 = make_float2(acc[nt][2], acc[nt][3]);
    }
}

// ---------------- kernel B: pool reduce, q, softmax over S, o (unchanged) ----
__global__ void __launch_bounds__(256) k_attn(
    const float* __restrict__ mask, const float* __restrict__ wq)
{
    const int r   = blockIdx.x;
    const int tid = threadIdx.x;
    const int lane = tid & 31;
    const int h    = tid >> 5;

    __shared__ float s_p[64];
    __shared__ float s_red[256];
    __shared__ float s_minv;

    if (tid < 32) {
        float mm = (lane < NSBLK) ? g_msump[r][lane] : 0.f;
        #pragma unroll
        for (int o = 16; o; o >>= 1) mm += __shfl_xor_sync(0xffffffffu, mm, o);
        if (lane == 0) s_minv = __fdividef(1.f, mm + 1e-10f);
    }
    {
        int c = tid & 63, gp = tid >> 6;
        float a = 0.f;
        #pragma unroll
        for (int k = 0; k < 4; ++k) a += g_poolp[r][gp * 4 + k][c];
        s_red[tid] = a;
    }
    __syncthreads();
    if (tid < 64)
        s_p[tid] = (s_red[tid] + s_red[tid + 64] + s_red[tid + 128] + s_red[tid + 192]) * s_minv;
    __syncthreads();

    float q[8];
    float pc0 = s_p[lane], pc1 = s_p[lane + 32];
    #pragma unroll
    for (int j = 0; j < 8; ++j)
        q[j] = pc0 * wq[lane * 64 + h * 8 + j] + pc1 * wq[(lane + 32) * 64 + h * 8 + j];
    #pragma unroll
    for (int o = 16; o; o >>= 1) {
        #pragma unroll
        for (int j = 0; j < 8; ++j) q[j] += __shfl_xor_sync(0xffffffffu, q[j], o);
    }
    #pragma unroll
    for (int j = 0; j < 8; ++j) q[j] *= 0.35355339059327373f;

    const float LOG2E = 1.4426950408889634f;
    float M = -1e30f, L = 0.f;
    float acc[8];
    #pragma unroll
    for (int j = 0; j < 8; ++j) acc[j] = 0.f;

    for (int t = 0; t < SDIM / 32; ++t) {
        int s = t * 32 + lane;
        const float4* kv = (const float4*)(g_kv + ((size_t)r * SDIM + s) * 16);
        float4 k0 = kv[0], k1 = kv[1];
        float4 v0 = kv[2], v1 = kv[3];
        float mv = __ldg(&mask[s * RDIM + r]);
        float logit = q[0]*k0.x + q[1]*k0.y + q[2]*k0.z + q[3]*k0.w
                    + q[4]*k1.x + q[5]*k1.y + q[6]*k1.z + q[7]*k1.w
                    + 1e9f * (mv - 1.f);
        float nM = fmaxf(M, logit);
        float sc = exp2f((M - nM) * LOG2E);
        float p  = exp2f((logit - nM) * LOG2E);
        L = L * sc + p;
        acc[0] = acc[0]*sc + p*v0.x; acc[1] = acc[1]*sc + p*v0.y;
        acc[2] = acc[2]*sc + p*v0.z; acc[3] = acc[3]*sc + p*v0.w;
        acc[4] = acc[4]*sc + p*v1.x; acc[5] = acc[5]*sc + p*v1.y;
        acc[6] = acc[6]*sc + p*v1.z; acc[7] = acc[7]*sc + p*v1.w;
        M = nM;
    }
    float Mm = M;
    #pragma unroll
    for (int o = 16; o; o >>= 1) Mm = fmaxf(Mm, __shfl_xor_sync(0xffffffffu, Mm, o));
    float sc = exp2f((M - Mm) * LOG2E);
    L *= sc;
    #pragma unroll
    for (int j = 0; j < 8; ++j) acc[j] *= sc;
    #pragma unroll
    for (int o = 16; o; o >>= 1) {
        L += __shfl_xor_sync(0xffffffffu, L, o);
        #pragma unroll
        for (int j = 0; j < 8; ++j) acc[j] += __shfl_xor_sync(0xffffffffu, acc[j], o);
    }
    if (lane == 0) {
        float inv = 1.f / L;
        #pragma unroll
        for (int j = 0; j < 8; ++j) g_ovec[r * 64 + h * 8 + j] = acc[j] * inv;
    }
}

// ===== kernel C: fp16 single-pass HMMA; XN loaded precomputed; 4 chunks =====
#define AS 72
#define BS 72
#define SMC_BYTES (128*AS*2 + 2*64*BS*2 + 2*64*4)   // 37376 B

__global__ void __launch_bounds__(256) k_out_mma(
    const float* __restrict__ wg, const float* __restrict__ bg,
    const float* __restrict__ wo, const float* __restrict__ bo,
    float* __restrict__ out)
{
    extern __shared__ __align__(16) uint8_t smraw[];
    __half* s_a  = (__half*)smraw;         // [128][AS] XN / later G (fp16)
    __half* s_b1 = s_a  + 128 * AS;        // [64][BS]  wg^T (fp16)
    __half* s_b2 = s_b1 + 64 * BS;         // [64][BS]  (ov.*wo)^T (fp16)
    float*  s_bg = (float*)(s_b2 + 64 * BS);
    float*  s_bo = s_bg + 64;

    const int r     = blockIdx.y;
    const int sbase = blockIdx.x * 512;    // quarter of S
    const int tid   = threadIdx.x;
    const int lane  = tid & 31;
    const int w     = tid >> 5;
    const int g     = lane >> 2;
    const int tig   = lane & 3;

    // ---- stage B1 = wg^T and B2 = (ov.*wo)^T once (fp16) ----
    const float* ov = g_ovec + r * 64;
    for (int idx = tid; idx < 4096; idx += 256) {
        int c = idx >> 6, j = idx & 63;            // wg[c][j]
        s_b1[j * BS + c] = __float2half_rn(__ldg(&wg[idx]));
        int jj = c, cc = j;                        // wo[jj][cc]
        s_b2[cc * BS + jj] = __float2half_rn(__ldg(&ov[jj]) * __ldg(&wo[idx]));
    }
    if (tid < 64) { s_bg[tid] = bg[tid]; s_bo[tid] = bo[tid]; }
    __syncthreads();   // B tiles + biases visible; warps free-run after

    const int ar0 = w * 16 + g;

    for (int chunk = 0; chunk < 4; ++chunk) {
        const int s0 = sbase + chunk * 128;

        // load precomputed XN(fp16): warp copies its 16 rows (4 rows x 8 chunks per pass)
        {
            const __half* gx = g_xn + ((size_t)r * SDIM + s0) * 64;
            const int rsub = lane >> 3;      // 0..3
            const int ch   = lane & 7;       // 0..7 (16B chunks)
            #pragma unroll
            for (int i = 0; i < 4; ++i) {
                const int row = w * 16 + i * 4 + rsub;
                uint4 v = *(const uint4*)(gx + (size_t)row * 64 + ch * 8);
                *(uint4*)&s_a[row * AS + ch * 8] = v;
            }
        }
        __syncwarp();

        // GEMM1: pre = XN @ wg  (fp16 single-pass)
        float acc[8][4];
        #pragma unroll
        for (int nt = 0; nt < 8; ++nt)
            #pragma unroll
            for (int q = 0; q < 4; ++q) acc[nt][q] = 0.f;

        #pragma unroll
        for (int kk = 0; kk < 4; ++kk) {
            const int k0 = kk * 16 + tig * 2;
            uint32_t a0 = ld32s(&s_a[ar0 * AS + k0]);
            uint32_t a1 = ld32s(&s_a[(ar0 + 8) * AS + k0]);
            uint32_t a2 = ld32s(&s_a[ar0 * AS + k0 + 8]);
            uint32_t a3 = ld32s(&s_a[(ar0 + 8) * AS + k0 + 8]);
            #pragma unroll
            for (int nt = 0; nt < 8; ++nt) {
                const int n = nt * 8 + g;
                uint32_t b0 = ld32s(&s_b1[n * BS + k0]);
                uint32_t b1 = ld32s(&s_b1[n * BS + k0 + 8]);
                mma_f16(acc[nt], a0, a1, a2, a3, b0, b1);
            }
        }
        __syncwarp();   // warp's GEMM1 reads of its A rows complete

        // epilogue 1: G = sigmoid(pre + bg) -> overwrite this warp's A rows
        #pragma unroll
        for (int nt = 0; nt < 8; ++nt) {
            const int col = nt * 8 + tig * 2;
            float v0 = sigm(acc[nt][0] + s_bg[col]);
            float v1 = sigm(acc[nt][1] + s_bg[col + 1]);
            float v2 = sigm(acc[nt][2] + s_bg[col]);
            float v3 = sigm(acc[nt][3] + s_bg[col + 1]);
            *(uint32_t*)&s_a[ar0 * AS + col]       = pack_h2(v0, v1);
            *(uint32_t*)&s_a[(ar0 + 8) * AS + col] = pack_h2(v2, v3);
        }
        __syncwarp();

        // GEMM2: out = G @ (ov.*wo) + bo
        float acc2[8][4];
        #pragma unroll
        for (int nt = 0; nt < 8; ++nt)
            #pragma unroll
            for (int q = 0; q < 4; ++q) acc2[nt][q] = 0.f;

        #pragma unroll
        for (int kk = 0; kk < 4; ++kk) {
            const int k0 = kk * 16 + tig * 2;
            uint32_t a0 = ld32s(&s_a[ar0 * AS + k0]);
            uint32_t a1 = ld32s(&s_a[(ar0 + 8) * AS + k0]);
            uint32_t a2 = ld32s(&s_a[ar0 * AS + k0 + 8]);
            uint32_t a3 = ld32s(&s_a[(ar0 + 8) * AS + k0 + 8]);
            #pragma unroll
            for (int nt = 0; nt < 8; ++nt) {
                const int n = nt * 8 + g;
                uint32_t b0 = ld32s(&s_b2[n * BS + k0]);
                uint32_t b1 = ld32s(&s_b2[n * BS + k0 + 8]);
                mma_f16(acc2[nt], a0, a1, a2, a3, b0, b1);
            }
        }

        // final store: + bo
        {
            const int row0 = sbase + chunk * 128 + ar0;
            float* op0 = out + ((size_t)row0 * RDIM + r) * CDIM;
            float* op1 = out + ((size_t)(row0 + 8) * RDIM + r) * CDIM;
            #pragma unroll
            for (int nt = 0; nt < 8; ++nt) {
                const int col = nt * 8 + tig * 2;
                float b0 = s_bo[col], b1 = s_bo[col + 1];
                *(float2*)(op0 + col) = make_float2(acc2[nt][0] + b0, acc2[nt][1] + b1);
                *(float2*)(op1 + col) = make_float2(acc2[nt][2] + b0, acc2[nt][3] + b1);
            }
        }
        __syncwarp();   // warp's GEMM2 reads done before next-chunk copy overwrites
    }
}

// ---------------------------------------------------------------------
extern "C" void kernel_launch(void* const* d_in, const int* in_sizes, int n_in,
                              void* d_out, int out_size) {
    const float* m    = (const float*)d_in[0];
    const float* mask = (const float*)d_in[1];
    const float* ln_w = (const float*)d_in[2];
    const float* ln_b = (const float*)d_in[3];
    const float* wq   = (const float*)d_in[4];
    const float* wk   = (const float*)d_in[5];
    const float* wv   = (const float*)d_in[6];
    const float* wg   = (const float*)d_in[7];
    const float* bg   = (const float*)d_in[8];
    const float* wo   = (const float*)d_in[9];
    const float* bo   = (const float*)d_in[10];
    float* out = (float*)d_out;

    cudaFuncSetAttribute(k_out_mma, cudaFuncAttributeMaxDynamicSharedMemorySize, SMC_BYTES);

    dim3 gA(NSBLK, RDIM);
    k_pool_kv<<<gA, 256>>>(m, mask, ln_w, ln_b, wk, wv);
    k_attn<<<RDIM, 256>>>(mask, wq);
    dim3 gC(4, RDIM);
    k_out_mma<<<gC, 256, SMC_BYTES>>>(wg, bg, wo, bo, out);
}

// round 16
// speedup vs baseline: 1.5511x; 1.0757x over previous
#include <cuda_runtime.h>
#include <cuda_bf16.h>
#include <cuda_fp16.h>
#include <math.h>
#include <stdint.h>

// Problem shape (fixed by setup_inputs)
#define SDIM 2048
#define RDIM 512
#define CDIM 64
#define NSBLK 16           // SDIM/128 blocks per r in kernel A
#define NPART 4            // softmax S-partitions in kernel B

// ---------------- device scratch (no allocs allowed) ----------------
static __device__ float  g_poolp[RDIM][NSBLK][64];        // per-(r, sblk) pool partials
static __device__ float  g_msump[RDIM][NSBLK];            // per-(r, sblk) mask-sum partials
static __device__ __half g_kvh[(size_t)RDIM * SDIM * 16]; // [r][s][j] fp16; j<8: k, j>=8: v
static __device__ float  g_part[RDIM][NPART][8][12];      // per (r,part,h): M, L, acc[8]
static __device__ __half g_xn[(size_t)RDIM * SDIM * 64];  // [r][s][c] LayerNorm(x) in fp16

__device__ __forceinline__ float sigm(float x) {
    float t = __expf(-x);
    return __fdividef(1.f, 1.f + t);
}
__device__ __forceinline__ void mma_bf16(float d[4],
    uint32_t a0, uint32_t a1, uint32_t a2, uint32_t a3,
    uint32_t b0, uint32_t b1)
{
    asm volatile(
        "mma.sync.aligned.m16n8k16.row.col.f32.bf16.bf16.f32 "
        "{%0,%1,%2,%3}, {%4,%5,%6,%7}, {%8,%9}, {%0,%1,%2,%3};"
        : "+f"(d[0]), "+f"(d[1]), "+f"(d[2]), "+f"(d[3])
        : "r"(a0), "r"(a1), "r"(a2), "r"(a3), "r"(b0), "r"(b1));
}
__device__ __forceinline__ void mma_f16(float d[4],
    uint32_t a0, uint32_t a1, uint32_t a2, uint32_t a3,
    uint32_t b0, uint32_t b1)
{
    asm volatile(
        "mma.sync.aligned.m16n8k16.row.col.f32.f16.f16.f32 "
        "{%0,%1,%2,%3}, {%4,%5,%6,%7}, {%8,%9}, {%0,%1,%2,%3};"
        : "+f"(d[0]), "+f"(d[1]), "+f"(d[2]), "+f"(d[3])
        : "r"(a0), "r"(a1), "r"(a2), "r"(a3), "r"(b0), "r"(b1));
}
__device__ __forceinline__ uint32_t ld32s(const void* p) {
    return *(const uint32_t*)p;
}
__device__ __forceinline__ uint32_t pack_h2(float x, float y) {
    __half2 h = __floats2half2_rn(x, y);
    return *(uint32_t*)&h;
}

// ========== kernel A: LN + masked pool + K/V(fp16) + XN(fp16) export ==========
#define ASTR 72
__global__ void __launch_bounds__(256) k_pool_kv(
    const float* __restrict__ m, const float* __restrict__ mask,
    const float* __restrict__ ln_w, const float* __restrict__ ln_b,
    const float* __restrict__ wk, const float* __restrict__ wv)
{
    __shared__ __nv_bfloat16 s_ah[128 * ASTR];   // XN hi, row-major [row][c]
    __shared__ __nv_bfloat16 s_al[128 * ASTR];   // XN lo
    __shared__ __nv_bfloat16 s_bh[16 * ASTR];    // wkv^T hi: [j][c]
    __shared__ __nv_bfloat16 s_bl[16 * ASTR];
    __shared__ float s_pool[8][64];
    __shared__ float s_ms[8];

    const int r    = blockIdx.y;
    const int s0   = blockIdx.x * 128;
    const int tid  = threadIdx.x;
    const int lane = tid & 31;
    const int w    = tid >> 5;
    const int g    = lane >> 2;
    const int tig  = lane & 3;

    for (int idx = tid; idx < 1024; idx += 256) {
        int j = idx >> 6, c = idx & 63;
        float v = (j < 8) ? __ldg(&wk[c * 8 + j]) : __ldg(&wv[c * 8 + (j - 8)]);
        __nv_bfloat16 h = __float2bfloat16(v);
        s_bh[j * ASTR + c] = h;
        s_bl[j * ASTR + c] = __float2bfloat16(v - __bfloat162float(h));
    }

    const float lw0 = ln_w[lane], lw1 = ln_w[lane + 32];
    const float lb0 = ln_b[lane], lb1 = ln_b[lane + 32];
    float p0 = 0.f, p1 = 0.f, pm = 0.f;
    #pragma unroll
    for (int i = 0; i < 16; ++i) {
        const int row = w * 16 + i;
        const int s   = s0 + row;
        const float* mp = m + ((size_t)s * RDIM + r) * CDIM;
        float x0 = mp[lane];
        float x1 = mp[lane + 32];
        float mv = __ldg(&mask[s * RDIM + r]);

        float sum = x0 + x1;
        #pragma unroll
        for (int o = 16; o; o >>= 1) sum += __shfl_xor_sync(0xffffffffu, sum, o);
        float mu = sum * (1.f / 64.f);
        float d0 = x0 - mu, d1 = x1 - mu;
        float vv = d0 * d0 + d1 * d1;
        #pragma unroll
        for (int o = 16; o; o >>= 1) vv += __shfl_xor_sync(0xffffffffu, vv, o);
        float rstd = rsqrtf(vv * (1.f / 64.f) + 1e-5f);
        float xn0 = d0 * rstd * lw0 + lb0;
        float xn1 = d1 * rstd * lw1 + lb1;

        __nv_bfloat16 h0 = __float2bfloat16(xn0);
        __nv_bfloat16 h1 = __float2bfloat16(xn1);
        s_ah[row * ASTR + lane]      = h0;
        s_ah[row * ASTR + lane + 32] = h1;
        s_al[row * ASTR + lane]      = __float2bfloat16(xn0 - __bfloat162float(h0));
        s_al[row * ASTR + lane + 32] = __float2bfloat16(xn1 - __bfloat162float(h1));

        // export XN in fp16 for kernel C
        __half* xp = g_xn + ((size_t)r * SDIM + s) * 64;
        xp[lane]      = __float2half_rn(xn0);
        xp[lane + 32] = __float2half_rn(xn1);

        p0 += xn0 * mv;
        p1 += xn1 * mv;
        pm += mv;   // identical across lanes
    }
    s_pool[w][lane]      = p0;
    s_pool[w][lane + 32] = p1;
    if (lane == 0) s_ms[w] = pm;
    __syncthreads();

    if (tid < 64) {
        float a = 0.f;
        #pragma unroll
        for (int k = 0; k < 8; ++k) a += s_pool[k][tid];
        g_poolp[r][blockIdx.x][tid] = a;
    }
    if (tid == 0) {
        float a = 0.f;
        #pragma unroll
        for (int k = 0; k < 8; ++k) a += s_ms[k];
        g_msump[r][blockIdx.x] = a;
    }

    const int ar0 = w * 16 + g;
    float acc[2][4];
    #pragma unroll
    for (int nt = 0; nt < 2; ++nt)
        #pragma unroll
        for (int q = 0; q < 4; ++q) acc[nt][q] = 0.f;

    #pragma unroll
    for (int kk = 0; kk < 4; ++kk) {
        const int k0 = kk * 16 + tig * 2;
        uint32_t ah0 = ld32s(&s_ah[ar0 * ASTR + k0]);
        uint32_t ah1 = ld32s(&s_ah[(ar0 + 8) * ASTR + k0]);
        uint32_t ah2 = ld32s(&s_ah[ar0 * ASTR + k0 + 8]);
        uint32_t ah3 = ld32s(&s_ah[(ar0 + 8) * ASTR + k0 + 8]);
        uint32_t al0 = ld32s(&s_al[ar0 * ASTR + k0]);
        uint32_t al1 = ld32s(&s_al[(ar0 + 8) * ASTR + k0]);
        uint32_t al2 = ld32s(&s_al[ar0 * ASTR + k0 + 8]);
        uint32_t al3 = ld32s(&s_al[(ar0 + 8) * ASTR + k0 + 8]);
        #pragma unroll
        for (int nt = 0; nt < 2; ++nt) {
            const int n = nt * 8 + g;
            uint32_t bh0 = ld32s(&s_bh[n * ASTR + k0]);
            uint32_t bh1 = ld32s(&s_bh[n * ASTR + k0 + 8]);
            uint32_t bl0 = ld32s(&s_bl[n * ASTR + k0]);
            uint32_t bl1 = ld32s(&s_bl[n * ASTR + k0 + 8]);
            mma_bf16(acc[nt], ah0, ah1, ah2, ah3, bh0, bh1);
            mma_bf16(acc[nt], ah0, ah1, ah2, ah3, bl0, bl1);
            mma_bf16(acc[nt], al0, al1, al2, al3, bh0, bh1);
        }
    }
    // store K/V as fp16 pairs: g_kvh[r][s][j]
    #pragma unroll
    for (int nt = 0; nt < 2; ++nt) {
        const int j0 = nt * 8 + tig * 2;
        const int sr = s0 + ar0;
        __half2 a01 = __floats2half2_rn(acc[nt][0], acc[nt][1]);
        __half2 a23 = __floats2half2_rn(acc[nt][2], acc[nt][3]);
        *(__half2*)(g_kvh + ((size_t)r * SDIM + sr) * 16 + j0)     = a01;
        *(__half2*)(g_kvh + ((size_t)r * SDIM + sr + 8) * 16 + j0) = a23;
    }
}

// ---- kernel B: pool reduce, q, PARTIAL softmax over S/4, unnormalized acc ----
// grid (NPART, RDIM); warp h = head h; lane strides s within the partition.
__global__ void __launch_bounds__(256) k_attn(
    const float* __restrict__ mask, const float* __restrict__ wq)
{
    const int part = blockIdx.x;
    const int r    = blockIdx.y;
    const int tid  = threadIdx.x;
    const int lane = tid & 31;
    const int h    = tid >> 5;

    __shared__ float s_p[64];
    __shared__ float s_red[256];
    __shared__ float s_minv;

    if (tid < 32) {
        float mm = (lane < NSBLK) ? g_msump[r][lane] : 0.f;
        #pragma unroll
        for (int o = 16; o; o >>= 1) mm += __shfl_xor_sync(0xffffffffu, mm, o);
        if (lane == 0) s_minv = __fdividef(1.f, mm + 1e-10f);
    }
    {
        int c = tid & 63, gp = tid >> 6;
        float a = 0.f;
        #pragma unroll
        for (int k = 0; k < 4; ++k) a += g_poolp[r][gp * 4 + k][c];
        s_red[tid] = a;
    }
    __syncthreads();
    if (tid < 64)
        s_p[tid] = (s_red[tid] + s_red[tid + 64] + s_red[tid + 128] + s_red[tid + 192]) * s_minv;
    __syncthreads();

    float q[8];
    float pc0 = s_p[lane], pc1 = s_p[lane + 32];
    #pragma unroll
    for (int j = 0; j < 8; ++j)
        q[j] = pc0 * wq[lane * 64 + h * 8 + j] + pc1 * wq[(lane + 32) * 64 + h * 8 + j];
    #pragma unroll
    for (int o = 16; o; o >>= 1) {
        #pragma unroll
        for (int j = 0; j < 8; ++j) q[j] += __shfl_xor_sync(0xffffffffu, q[j], o);
    }
    #pragma unroll
    for (int j = 0; j < 8; ++j) q[j] *= 0.35355339059327373f;

    const float LOG2E = 1.4426950408889634f;
    float M = -1e30f, L = 0.f;
    float acc[8];
    #pragma unroll
    for (int j = 0; j < 8; ++j) acc[j] = 0.f;

    const int sp0 = part * (SDIM / NPART);
    for (int t = 0; t < (SDIM / NPART) / 32; ++t) {
        int s = sp0 + t * 32 + lane;
        const __half2* kvp = (const __half2*)(g_kvh + ((size_t)r * SDIM + s) * 16);
        uint4 raw0 = *(const uint4*)kvp;        // k0..k7
        uint4 raw1 = *(const uint4*)(kvp + 4);  // v0..v7
        const __half2* kh = (const __half2*)&raw0;
        const __half2* vh = (const __half2*)&raw1;
        float2 k01 = __half22float2(kh[0]), k23 = __half22float2(kh[1]);
        float2 k45 = __half22float2(kh[2]), k67 = __half22float2(kh[3]);
        float2 v01 = __half22float2(vh[0]), v23 = __half22float2(vh[1]);
        float2 v45 = __half22float2(vh[2]), v67 = __half22float2(vh[3]);
        float mv = __ldg(&mask[s * RDIM + r]);
        float logit = q[0]*k01.x + q[1]*k01.y + q[2]*k23.x + q[3]*k23.y
                    + q[4]*k45.x + q[5]*k45.y + q[6]*k67.x + q[7]*k67.y
                    + 1e9f * (mv - 1.f);
        float nM = fmaxf(M, logit);
        float sc = exp2f((M - nM) * LOG2E);
        float p  = exp2f((logit - nM) * LOG2E);
        L = L * sc + p;
        acc[0] = acc[0]*sc + p*v01.x; acc[1] = acc[1]*sc + p*v01.y;
        acc[2] = acc[2]*sc + p*v23.x; acc[3] = acc[3]*sc + p*v23.y;
        acc[4] = acc[4]*sc + p*v45.x; acc[5] = acc[5]*sc + p*v45.y;
        acc[6] = acc[6]*sc + p*v67.x; acc[7] = acc[7]*sc + p*v67.y;
        M = nM;
    }
    // merge lanes
    float Mm = M;
    #pragma unroll
    for (int o = 16; o; o >>= 1) Mm = fmaxf(Mm, __shfl_xor_sync(0xffffffffu, Mm, o));
    float sc = exp2f((M - Mm) * LOG2E);
    L *= sc;
    #pragma unroll
    for (int j = 0; j < 8; ++j) acc[j] *= sc;
    #pragma unroll
    for (int o = 16; o; o >>= 1) {
        L += __shfl_xor_sync(0xffffffffu, L, o);
        #pragma unroll
        for (int j = 0; j < 8; ++j) acc[j] += __shfl_xor_sync(0xffffffffu, acc[j], o);
    }
    if (lane == 0) {
        float* gp = &g_part[r][part][h][0];
        gp[0] = Mm;
        gp[1] = L;
        #pragma unroll
        for (int j = 0; j < 8; ++j) gp[2 + j] = acc[j];   // unnormalized
    }
}

// ===== kernel C: partial-softmax merge + fp16 single-pass HMMA; 4 chunks =====
#define AS 72
#define BS 72
#define SMC_BYTES (128*AS*2 + 2*64*BS*2 + 3*64*4)   // 37632 B

__global__ void __launch_bounds__(256) k_out_mma(
    const float* __restrict__ wg, const float* __restrict__ bg,
    const float* __restrict__ wo, const float* __restrict__ bo,
    float* __restrict__ out)
{
    extern __shared__ __align__(16) uint8_t smraw[];
    __half* s_a  = (__half*)smraw;         // [128][AS] XN / later G (fp16)
    __half* s_b1 = s_a  + 128 * AS;        // [64][BS]  wg^T (fp16)
    __half* s_b2 = s_b1 + 64 * BS;         // [64][BS]  (ov.*wo)^T (fp16)
    float*  s_bg = (float*)(s_b2 + 64 * BS);
    float*  s_bo = s_bg + 64;
    float*  s_ov = s_bo + 64;

    const int r     = blockIdx.y;
    const int sbase = blockIdx.x * 512;    // quarter of S
    const int tid   = threadIdx.x;
    const int lane  = tid & 31;
    const int w     = tid >> 5;
    const int g     = lane >> 2;
    const int tig   = lane & 3;

    // ---- merge softmax partials -> o vector (exact flash-style merge) ----
    if (tid < 64) {
        const int h = tid >> 3, ch = tid & 7;
        float Mp[NPART], Lp[NPART], ap[NPART];
        #pragma unroll
        for (int p = 0; p < NPART; ++p) {
            const float* gp = &g_part[r][p][h][0];
            Mp[p] = gp[0]; Lp[p] = gp[1]; ap[p] = gp[2 + ch];
        }
        float M = fmaxf(fmaxf(Mp[0], Mp[1]), fmaxf(Mp[2], Mp[3]));
        float Ls = 0.f, as = 0.f;
        #pragma unroll
        for (int p = 0; p < NPART; ++p) {
            float wgt = __expf(Mp[p] - M);
            Ls += Lp[p] * wgt;
            as += ap[p] * wgt;
        }
        s_ov[tid] = as / Ls;
    }
    __syncthreads();

    // ---- stage B1 = wg^T and B2 = (ov.*wo)^T once (fp16) ----
    for (int idx = tid; idx < 4096; idx += 256) {
        int c = idx >> 6, j = idx & 63;            // wg[c][j]
        s_b1[j * BS + c] = __float2half_rn(__ldg(&wg[idx]));
        int jj = c, cc = j;                        // wo[jj][cc]
        s_b2[cc * BS + jj] = __float2half_rn(s_ov[jj] * __ldg(&wo[idx]));
    }
    if (tid < 64) { s_bg[tid] = bg[tid]; s_bo[tid] = bo[tid]; }
    __syncthreads();   // B tiles + biases visible; warps free-run after

    const int ar0 = w * 16 + g;

    for (int chunk = 0; chunk < 4; ++chunk) {
        const int s0 = sbase + chunk * 128;

        // load precomputed XN(fp16): warp copies its 16 rows
        {
            const __half* gx = g_xn + ((size_t)r * SDIM + s0) * 64;
            const int rsub = lane >> 3;      // 0..3
            const int ch   = lane & 7;       // 0..7 (16B chunks)
            #pragma unroll
            for (int i = 0; i < 4; ++i) {
                const int row = w * 16 + i * 4 + rsub;
                uint4 v = *(const uint4*)(gx + (size_t)row * 64 + ch * 8);
                *(uint4*)&s_a[row * AS + ch * 8] = v;
            }
        }
        __syncwarp();

        // GEMM1: pre = XN @ wg  (fp16 single-pass)
        float acc[8][4];
        #pragma unroll
        for (int nt = 0; nt < 8; ++nt)
            #pragma unroll
            for (int q = 0; q < 4; ++q) acc[nt][q] = 0.f;

        #pragma unroll
        for (int kk = 0; kk < 4; ++kk) {
            const int k0 = kk * 16 + tig * 2;
            uint32_t a0 = ld32s(&s_a[ar0 * AS + k0]);
            uint32_t a1 = ld32s(&s_a[(ar0 + 8) * AS + k0]);
            uint32_t a2 = ld32s(&s_a[ar0 * AS + k0 + 8]);
            uint32_t a3 = ld32s(&s_a[(ar0 + 8) * AS + k0 + 8]);
            #pragma unroll
            for (int nt = 0; nt < 8; ++nt) {
                const int n = nt * 8 + g;
                uint32_t b0 = ld32s(&s_b1[n * BS + k0]);
                uint32_t b1 = ld32s(&s_b1[n * BS + k0 + 8]);
                mma_f16(acc[nt], a0, a1, a2, a3, b0, b1);
            }
        }
        __syncwarp();   // warp's GEMM1 reads of its A rows complete

        // epilogue 1: G = sigmoid(pre + bg) -> overwrite this warp's A rows
        #pragma unroll
        for (int nt = 0; nt < 8; ++nt) {
            const int col = nt * 8 + tig * 2;
            float v0 = sigm(acc[nt][0] + s_bg[col]);
            float v1 = sigm(acc[nt][1] + s_bg[col + 1]);
            float v2 = sigm(acc[nt][2] + s_bg[col]);
            float v3 = sigm(acc[nt][3] + s_bg[col + 1]);
            *(uint32_t*)&s_a[ar0 * AS + col]       = pack_h2(v0, v1);
            *(uint32_t*)&s_a[(ar0 + 8) * AS + col] = pack_h2(v2, v3);
        }
        __syncwarp();

        // GEMM2: out = G @ (ov.*wo) + bo
        float acc2[8][4];
        #pragma unroll
        for (int nt = 0; nt < 8; ++nt)
            #pragma unroll
            for (int q = 0; q < 4; ++q) acc2[nt][q] = 0.f;

        #pragma unroll
        for (int kk = 0; kk < 4; ++kk) {
            const int k0 = kk * 16 + tig * 2;
            uint32_t a0 = ld32s(&s_a[ar0 * AS + k0]);
            uint32_t a1 = ld32s(&s_a[(ar0 + 8) * AS + k0]);
            uint32_t a2 = ld32s(&s_a[ar0 * AS + k0 + 8]);
            uint32_t a3 = ld32s(&s_a[(ar0 + 8) * AS + k0 + 8]);
            #pragma unroll
            for (int nt = 0; nt < 8; ++nt) {
                const int n = nt * 8 + g;
                uint32_t b0 = ld32s(&s_b2[n * BS + k0]);
                uint32_t b1 = ld32s(&s_b2[n * BS + k0 + 8]);
                mma_f16(acc2[nt], a0, a1, a2, a3, b0, b1);
            }
        }

        // final store: + bo
        {
            const int row0 = sbase + chunk * 128 + ar0;
            float* op0 = out + ((size_t)row0 * RDIM + r) * CDIM;
            float* op1 = out + ((size_t)(row0 + 8) * RDIM + r) * CDIM;
            #pragma unroll
            for (int nt = 0; nt < 8; ++nt) {
                const int col = nt * 8 + tig * 2;
                float b0 = s_bo[col], b1 = s_bo[col + 1];
                *(float2*)(op0 + col) = make_float2(acc2[nt][0] + b0, acc2[nt][1] + b1);
                *(float2*)(op1 + col) = make_float2(acc2[nt][2] + b0, acc2[nt][3] + b1);
            }
        }
        __syncwarp();   // warp's GEMM2 reads done before next-chunk copy overwrites
    }
}

// ---------------------------------------------------------------------
extern "C" void kernel_launch(void* const* d_in, const int* in_sizes, int n_in,
                              void* d_out, int out_size) {
    const float* m    = (const float*)d_in[0];
    const float* mask = (const float*)d_in[1];
    const float* ln_w = (const float*)d_in[2];
    const float* ln_b = (const float*)d_in[3];
    const float* wq   = (const float*)d_in[4];
    const float* wk   = (const float*)d_in[5];
    const float* wv   = (const float*)d_in[6];
    const float* wg   = (const float*)d_in[7];
    const float* bg   = (const float*)d_in[8];
    const float* wo   = (const float*)d_in[9];
    const float* bo   = (const float*)d_in[10];
    float* out = (float*)d_out;

    cudaFuncSetAttribute(k_out_mma, cudaFuncAttributeMaxDynamicSharedMemorySize, SMC_BYTES);

    dim3 gA(NSBLK, RDIM);
    k_pool_kv<<<gA, 256>>>(m, mask, ln_w, ln_b, wk, wv);
    dim3 gB(NPART, RDIM);
    k_attn<<<gB, 256>>>(mask, wq);
    dim3 gC(4, RDIM);
    k_out_mma<<<gC, 256, SMC_BYTES>>>(wg, bg, wo, bo, out);
}

// round 17
// speedup vs baseline: 1.7319x; 1.1166x over previous
#include <cuda_runtime.h>
#include <cuda_fp16.h>
#include <math.h>
#include <stdint.h>

// Problem shape (fixed by setup_inputs)
#define SDIM 2048
#define RDIM 512
#define CDIM 64
#define NSBLK 16           // SDIM/128 blocks per r in kernel A
#define NPART 4            // softmax S-partitions in kernel B

// ---------------- device scratch (no allocs allowed) ----------------
static __device__ float  g_poolp[RDIM][NSBLK][64];        // per-(r, sblk) pool partials
static __device__ float  g_msump[RDIM][NSBLK];            // per-(r, sblk) mask-sum partials
static __device__ __half g_kvh[(size_t)RDIM * SDIM * 16]; // [r][s][j] fp16; j<8: k, j>=8: v
static __device__ float  g_part[RDIM][NPART][8][12];      // per (r,part,h): M, L, acc[8]
static __device__ __half g_xn[(size_t)RDIM * SDIM * 64];  // [r][s][c] LayerNorm(x) in fp16

__device__ __forceinline__ float sigm(float x) {
    float t = __expf(-x);
    return __fdividef(1.f, 1.f + t);
}
__device__ __forceinline__ void mma_f16(float d[4],
    uint32_t a0, uint32_t a1, uint32_t a2, uint32_t a3,
    uint32_t b0, uint32_t b1)
{
    asm volatile(
        "mma.sync.aligned.m16n8k16.row.col.f32.f16.f16.f32 "
        "{%0,%1,%2,%3}, {%4,%5,%6,%7}, {%8,%9}, {%0,%1,%2,%3};"
        : "+f"(d[0]), "+f"(d[1]), "+f"(d[2]), "+f"(d[3])
        : "r"(a0), "r"(a1), "r"(a2), "r"(a3), "r"(b0), "r"(b1));
}
__device__ __forceinline__ uint32_t ld32s(const void* p) {
    return *(const uint32_t*)p;
}
__device__ __forceinline__ uint32_t pack_h2(float x, float y) {
    __half2 h = __floats2half2_rn(x, y);
    return *(uint32_t*)&h;
}

// ========== kernel A: LN + masked pool + K/V(fp16 MMA) + XN(fp16) export ==========
// fp16-native: one XN tile serves both the g_xn export and the K/V MMA.
#define ASTR 72
__global__ void __launch_bounds__(256) k_pool_kv(
    const float* __restrict__ m, const float* __restrict__ mask,
    const float* __restrict__ ln_w, const float* __restrict__ ln_b,
    const float* __restrict__ wk, const float* __restrict__ wv)
{
    __shared__ __half s_x[128 * ASTR];   // XN fp16, row-major [row][c]
    __shared__ __half s_b[16 * ASTR];    // wkv^T fp16: [j][c]
    __shared__ float s_pool[8][64];
    __shared__ float s_ms[8];

    const int r    = blockIdx.y;
    const int s0   = blockIdx.x * 128;
    const int tid  = threadIdx.x;
    const int lane = tid & 31;
    const int w    = tid >> 5;
    const int g    = lane >> 2;
    const int tig  = lane & 3;

    for (int idx = tid; idx < 1024; idx += 256) {
        int j = idx >> 6, c = idx & 63;
        float v = (j < 8) ? __ldg(&wk[c * 8 + j]) : __ldg(&wv[c * 8 + (j - 8)]);
        s_b[j * ASTR + c] = __float2half_rn(v);
    }

    const float lw0 = ln_w[lane], lw1 = ln_w[lane + 32];
    const float lb0 = ln_b[lane], lb1 = ln_b[lane + 32];
    float p0 = 0.f, p1 = 0.f, pm = 0.f;
    #pragma unroll
    for (int i = 0; i < 16; ++i) {
        const int row = w * 16 + i;
        const int s   = s0 + row;
        const float* mp = m + ((size_t)s * RDIM + r) * CDIM;
        float x0 = mp[lane];
        float x1 = mp[lane + 32];
        float mv = __ldg(&mask[s * RDIM + r]);

        float sum = x0 + x1;
        #pragma unroll
        for (int o = 16; o; o >>= 1) sum += __shfl_xor_sync(0xffffffffu, sum, o);
        float mu = sum * (1.f / 64.f);
        float d0 = x0 - mu, d1 = x1 - mu;
        float vv = d0 * d0 + d1 * d1;
        #pragma unroll
        for (int o = 16; o; o >>= 1) vv += __shfl_xor_sync(0xffffffffu, vv, o);
        float rstd = rsqrtf(vv * (1.f / 64.f) + 1e-5f);
        float xn0 = d0 * rstd * lw0 + lb0;
        float xn1 = d1 * rstd * lw1 + lb1;

        __half h0 = __float2half_rn(xn0);
        __half h1 = __float2half_rn(xn1);
        s_x[row * ASTR + lane]      = h0;
        s_x[row * ASTR + lane + 32] = h1;

        // export XN fp16 for kernel C (same values as the smem tile)
        __half* xp = g_xn + ((size_t)r * SDIM + s) * 64;
        xp[lane]      = h0;
        xp[lane + 32] = h1;

        p0 += xn0 * mv;
        p1 += xn1 * mv;
        pm += mv;   // identical across lanes
    }
    s_pool[w][lane]      = p0;
    s_pool[w][lane + 32] = p1;
    if (lane == 0) s_ms[w] = pm;
    __syncthreads();

    if (tid < 64) {
        float a = 0.f;
        #pragma unroll
        for (int k = 0; k < 8; ++k) a += s_pool[k][tid];
        g_poolp[r][blockIdx.x][tid] = a;
    }
    if (tid == 0) {
        float a = 0.f;
        #pragma unroll
        for (int k = 0; k < 8; ++k) a += s_ms[k];
        g_msump[r][blockIdx.x] = a;
    }

    // K/V GEMM via fp16 single-pass HMMA: XN[16 rows] @ wkv^T -> 16 j outputs
    const int ar0 = w * 16 + g;
    float acc[2][4];
    #pragma unroll
    for (int nt = 0; nt < 2; ++nt)
        #pragma unroll
        for (int q = 0; q < 4; ++q) acc[nt][q] = 0.f;

    #pragma unroll
    for (int kk = 0; kk < 4; ++kk) {
        const int k0 = kk * 16 + tig * 2;
        uint32_t a0 = ld32s(&s_x[ar0 * ASTR + k0]);
        uint32_t a1 = ld32s(&s_x[(ar0 + 8) * ASTR + k0]);
        uint32_t a2 = ld32s(&s_x[ar0 * ASTR + k0 + 8]);
        uint32_t a3 = ld32s(&s_x[(ar0 + 8) * ASTR + k0 + 8]);
        #pragma unroll
        for (int nt = 0; nt < 2; ++nt) {
            const int n = nt * 8 + g;
            uint32_t b0 = ld32s(&s_b[n * ASTR + k0]);
            uint32_t b1 = ld32s(&s_b[n * ASTR + k0 + 8]);
            mma_f16(acc[nt], a0, a1, a2, a3, b0, b1);
        }
    }
    // store K/V as fp16 pairs: g_kvh[r][s][j]
    #pragma unroll
    for (int nt = 0; nt < 2; ++nt) {
        const int j0 = nt * 8 + tig * 2;
        const int sr = s0 + ar0;
        __half2 a01 = __floats2half2_rn(acc[nt][0], acc[nt][1]);
        __half2 a23 = __floats2half2_rn(acc[nt][2], acc[nt][3]);
        *(__half2*)(g_kvh + ((size_t)r * SDIM + sr) * 16 + j0)     = a01;
        *(__half2*)(g_kvh + ((size_t)r * SDIM + sr + 8) * 16 + j0) = a23;
    }
}

// ---- kernel B: pool reduce, q, PARTIAL softmax over S/4, unnormalized acc ----
__global__ void __launch_bounds__(256) k_attn(
    const float* __restrict__ mask, const float* __restrict__ wq)
{
    const int part = blockIdx.x;
    const int r    = blockIdx.y;
    const int tid  = threadIdx.x;
    const int lane = tid & 31;
    const int h    = tid >> 5;

    __shared__ float s_p[64];
    __shared__ float s_red[256];
    __shared__ float s_minv;

    if (tid < 32) {
        float mm = (lane < NSBLK) ? g_msump[r][lane] : 0.f;
        #pragma unroll
        for (int o = 16; o; o >>= 1) mm += __shfl_xor_sync(0xffffffffu, mm, o);
        if (lane == 0) s_minv = __fdividef(1.f, mm + 1e-10f);
    }
    {
        int c = tid & 63, gp = tid >> 6;
        float a = 0.f;
        #pragma unroll
        for (int k = 0; k < 4; ++k) a += g_poolp[r][gp * 4 + k][c];
        s_red[tid] = a;
    }
    __syncthreads();
    if (tid < 64)
        s_p[tid] = (s_red[tid] + s_red[tid + 64] + s_red[tid + 128] + s_red[tid + 192]) * s_minv;
    __syncthreads();

    float q[8];
    float pc0 = s_p[lane], pc1 = s_p[lane + 32];
    #pragma unroll
    for (int j = 0; j < 8; ++j)
        q[j] = pc0 * wq[lane * 64 + h * 8 + j] + pc1 * wq[(lane + 32) * 64 + h * 8 + j];
    #pragma unroll
    for (int o = 16; o; o >>= 1) {
        #pragma unroll
        for (int j = 0; j < 8; ++j) q[j] += __shfl_xor_sync(0xffffffffu, q[j], o);
    }
    #pragma unroll
    for (int j = 0; j < 8; ++j) q[j] *= 0.35355339059327373f;

    const float LOG2E = 1.4426950408889634f;
    float M = -1e30f, L = 0.f;
    float acc[8];
    #pragma unroll
    for (int j = 0; j < 8; ++j) acc[j] = 0.f;

    const int sp0 = part * (SDIM / NPART);
    for (int t = 0; t < (SDIM / NPART) / 32; ++t) {
        int s = sp0 + t * 32 + lane;
        const __half2* kvp = (const __half2*)(g_kvh + ((size_t)r * SDIM + s) * 16);
        uint4 raw0 = *(const uint4*)kvp;        // k0..k7
        uint4 raw1 = *(const uint4*)(kvp + 4);  // v0..v7
        const __half2* kh = (const __half2*)&raw0;
        const __half2* vh = (const __half2*)&raw1;
        float2 k01 = __half22float2(kh[0]), k23 = __half22float2(kh[1]);
        float2 k45 = __half22float2(kh[2]), k67 = __half22float2(kh[3]);
        float2 v01 = __half22float2(vh[0]), v23 = __half22float2(vh[1]);
        float2 v45 = __half22float2(vh[2]), v67 = __half22float2(vh[3]);
        float mv = __ldg(&mask[s * RDIM + r]);
        float logit = q[0]*k01.x + q[1]*k01.y + q[2]*k23.x + q[3]*k23.y
                    + q[4]*k45.x + q[5]*k45.y + q[6]*k67.x + q[7]*k67.y
                    + 1e9f * (mv - 1.f);
        float nM = fmaxf(M, logit);
        float sc = exp2f((M - nM) * LOG2E);
        float p  = exp2f((logit - nM) * LOG2E);
        L = L * sc + p;
        acc[0] = acc[0]*sc + p*v01.x; acc[1] = acc[1]*sc + p*v01.y;
        acc[2] = acc[2]*sc + p*v23.x; acc[3] = acc[3]*sc + p*v23.y;
        acc[4] = acc[4]*sc + p*v45.x; acc[5] = acc[5]*sc + p*v45.y;
        acc[6] = acc[6]*sc + p*v67.x; acc[7] = acc[7]*sc + p*v67.y;
        M = nM;
    }
    float Mm = M;
    #pragma unroll
    for (int o = 16; o; o >>= 1) Mm = fmaxf(Mm, __shfl_xor_sync(0xffffffffu, Mm, o));
    float sc = exp2f((M - Mm) * LOG2E);
    L *= sc;
    #pragma unroll
    for (int j = 0; j < 8; ++j) acc[j] *= sc;
    #pragma unroll
    for (int o = 16; o; o >>= 1) {
        L += __shfl_xor_sync(0xffffffffu, L, o);
        #pragma unroll
        for (int j = 0; j < 8; ++j) acc[j] += __shfl_xor_sync(0xffffffffu, acc[j], o);
    }
    if (lane == 0) {
        float* gp = &g_part[r][part][h][0];
        gp[0] = Mm;
        gp[1] = L;
        #pragma unroll
        for (int j = 0; j < 8; ++j) gp[2 + j] = acc[j];   // unnormalized
    }
}

// ===== kernel C: partial-softmax merge + fp16 single-pass HMMA; 4 chunks =====
#define AS 72
#define BS 72
#define SMC_BYTES (128*AS*2 + 2*64*BS*2 + 3*64*4)   // 37632 B

__global__ void __launch_bounds__(256) k_out_mma(
    const float* __restrict__ wg, const float* __restrict__ bg,
    const float* __restrict__ wo, const float* __restrict__ bo,
    float* __restrict__ out)
{
    extern __shared__ __align__(16) uint8_t smraw[];
    __half* s_a  = (__half*)smraw;         // [128][AS] XN / later G (fp16)
    __half* s_b1 = s_a  + 128 * AS;        // [64][BS]  wg^T (fp16)
    __half* s_b2 = s_b1 + 64 * BS;         // [64][BS]  (ov.*wo)^T (fp16)
    float*  s_bg = (float*)(s_b2 + 64 * BS);
    float*  s_bo = s_bg + 64;
    float*  s_ov = s_bo + 64;

    const int r     = blockIdx.y;
    const int sbase = blockIdx.x * 512;    // quarter of S
    const int tid   = threadIdx.x;
    const int lane  = tid & 31;
    const int w     = tid >> 5;
    const int g     = lane >> 2;
    const int tig   = lane & 3;

    // ---- merge softmax partials -> o vector (exact flash-style merge) ----
    if (tid < 64) {
        const int h = tid >> 3, ch = tid & 7;
        float Mp[NPART], Lp[NPART], ap[NPART];
        #pragma unroll
        for (int p = 0; p < NPART; ++p) {
            const float* gp = &g_part[r][p][h][0];
            Mp[p] = gp[0]; Lp[p] = gp[1]; ap[p] = gp[2 + ch];
        }
        float M = fmaxf(fmaxf(Mp[0], Mp[1]), fmaxf(Mp[2], Mp[3]));
        float Ls = 0.f, as = 0.f;
        #pragma unroll
        for (int p = 0; p < NPART; ++p) {
            float wgt = __expf(Mp[p] - M);
            Ls += Lp[p] * wgt;
            as += ap[p] * wgt;
        }
        s_ov[tid] = as / Ls;
    }
    __syncthreads();

    // ---- stage B1 = wg^T and B2 = (ov.*wo)^T once (fp16) ----
    for (int idx = tid; idx < 4096; idx += 256) {
        int c = idx >> 6, j = idx & 63;            // wg[c][j]
        s_b1[j * BS + c] = __float2half_rn(__ldg(&wg[idx]));
        int jj = c, cc = j;                        // wo[jj][cc]
        s_b2[cc * BS + jj] = __float2half_rn(s_ov[jj] * __ldg(&wo[idx]));
    }
    if (tid < 64) { s_bg[tid] = bg[tid]; s_bo[tid] = bo[tid]; }
    __syncthreads();   // B tiles + biases visible; warps free-run after

    const int ar0 = w * 16 + g;

    for (int chunk = 0; chunk < 4; ++chunk) {
        const int s0 = sbase + chunk * 128;

        // load precomputed XN(fp16): warp copies its 16 rows
        {
            const __half* gx = g_xn + ((size_t)r * SDIM + s0) * 64;
            const int rsub = lane >> 3;      // 0..3
            const int ch   = lane & 7;       // 0..7 (16B chunks)
            #pragma unroll
            for (int i = 0; i < 4; ++i) {
                const int row = w * 16 + i * 4 + rsub;
                uint4 v = *(const uint4*)(gx + (size_t)row * 64 + ch * 8);
                *(uint4*)&s_a[row * AS + ch * 8] = v;
            }
        }
        __syncwarp();

        // GEMM1: pre = XN @ wg  (fp16 single-pass)
        float acc[8][4];
        #pragma unroll
        for (int nt = 0; nt < 8; ++nt)
            #pragma unroll
            for (int q = 0; q < 4; ++q) acc[nt][q] = 0.f;

        #pragma unroll
        for (int kk = 0; kk < 4; ++kk) {
            const int k0 = kk * 16 + tig * 2;
            uint32_t a0 = ld32s(&s_a[ar0 * AS + k0]);
            uint32_t a1 = ld32s(&s_a[(ar0 + 8) * AS + k0]);
            uint32_t a2 = ld32s(&s_a[ar0 * AS + k0 + 8]);
            uint32_t a3 = ld32s(&s_a[(ar0 + 8) * AS + k0 + 8]);
            #pragma unroll
            for (int nt = 0; nt < 8; ++nt) {
                const int n = nt * 8 + g;
                uint32_t b0 = ld32s(&s_b1[n * BS + k0]);
                uint32_t b1 = ld32s(&s_b1[n * BS + k0 + 8]);
                mma_f16(acc[nt], a0, a1, a2, a3, b0, b1);
            }
        }
        __syncwarp();   // warp's GEMM1 reads of its A rows complete

        // epilogue 1: G = sigmoid(pre + bg) -> overwrite this warp's A rows
        #pragma unroll
        for (int nt = 0; nt < 8; ++nt) {
            const int col = nt * 8 + tig * 2;
            float v0 = sigm(acc[nt][0] + s_bg[col]);
            float v1 = sigm(acc[nt][1] + s_bg[col + 1]);
            float v2 = sigm(acc[nt][2] + s_bg[col]);
            float v3 = sigm(acc[nt][3] + s_bg[col + 1]);
            *(uint32_t*)&s_a[ar0 * AS + col]       = pack_h2(v0, v1);
            *(uint32_t*)&s_a[(ar0 + 8) * AS + col] = pack_h2(v2, v3);
        }
        __syncwarp();

        // GEMM2: out = G @ (ov.*wo) + bo
        float acc2[8][4];
        #pragma unroll
        for (int nt = 0; nt < 8; ++nt)
            #pragma unroll
            for (int q = 0; q < 4; ++q) acc2[nt][q] = 0.f;

        #pragma unroll
        for (int kk = 0; kk < 4; ++kk) {
            const int k0 = kk * 16 + tig * 2;
            uint32_t a0 = ld32s(&s_a[ar0 * AS + k0]);
            uint32_t a1 = ld32s(&s_a[(ar0 + 8) * AS + k0]);
            uint32_t a2 = ld32s(&s_a[ar0 * AS + k0 + 8]);
            uint32_t a3 = ld32s(&s_a[(ar0 + 8) * AS + k0 + 8]);
            #pragma unroll
            for (int nt = 0; nt < 8; ++nt) {
                const int n = nt * 8 + g;
                uint32_t b0 = ld32s(&s_b2[n * BS + k0]);
                uint32_t b1 = ld32s(&s_b2[n * BS + k0 + 8]);
                mma_f16(acc2[nt], a0, a1, a2, a3, b0, b1);
            }
        }

        // final store: + bo
        {
            const int row0 = sbase + chunk * 128 + ar0;
            float* op0 = out + ((size_t)row0 * RDIM + r) * CDIM;
            float* op1 = out + ((size_t)(row0 + 8) * RDIM + r) * CDIM;
            #pragma unroll
            for (int nt = 0; nt < 8; ++nt) {
                const int col = nt * 8 + tig * 2;
                float b0 = s_bo[col], b1 = s_bo[col + 1];
                *(float2*)(op0 + col) = make_float2(acc2[nt][0] + b0, acc2[nt][1] + b1);
                *(float2*)(op1 + col) = make_float2(acc2[nt][2] + b0, acc2[nt][3] + b1);
            }
        }
        __syncwarp();   // warp's GEMM2 reads done before next-chunk copy overwrites
    }
}

// ---------------------------------------------------------------------
extern "C" void kernel_launch(void* const* d_in, const int* in_sizes, int n_in,
                              void* d_out, int out_size) {
    const float* m    = (const float*)d_in[0];
    const float* mask = (const float*)d_in[1];
    const float* ln_w = (const float*)d_in[2];
    const float* ln_b = (const float*)d_in[3];
    const float* wq   = (const float*)d_in[4];
    const float* wk   = (const float*)d_in[5];
    const float* wv   = (const float*)d_in[6];
    const float* wg   = (const float*)d_in[7];
    const float* bg   = (const float*)d_in[8];
    const float* wo   = (const float*)d_in[9];
    const float* bo   = (const float*)d_in[10];
    float* out = (float*)d_out;

    cudaFuncSetAttribute(k_out_mma, cudaFuncAttributeMaxDynamicSharedMemorySize, SMC_BYTES);

    dim3 gA(NSBLK, RDIM);
    k_pool_kv<<<gA, 256>>>(m, mask, ln_w, ln_b, wk, wv);
    dim3 gB(NPART, RDIM);
    k_attn<<<gB, 256>>>(mask, wq);
    dim3 gC(4, RDIM);
    k_out_mma<<<gC, 256, SMC_BYTES>>>(wg, bg, wo, bo, out);
}